// round 15
// baseline (speedup 1.0000x reference)
#include <cuda_runtime.h>
#include <cuda_fp16.h>
#include <cstdint>

#define N_NODES 40000
#define N_PAD   40064   // 313 * 128
#define N_EDGES 640000
#define HID 128
#define N_LAYERS 4
#define NUM_GRAPHS 256

#define GT 256          // 8 warps per GEMM CTA

#define LDB 272
#define TILE_BYTES 34816
#define SMEM_1 34816
#define SMEM_2 69632

// ---------------------------------------------------------------------------
// Scratch
// ---------------------------------------------------------------------------
__device__ uint4 g_hbf[2][(size_t)N_PAD * 32];
__device__ uint4 g_uv[4][(size_t)N_PAD * 32];      // u0,u1,v0,v1 ping-pong
__device__ float g_T[(size_t)N_PAD * 16];          // scattered raw edge feats
__device__ float g_S[(size_t)N_PAD * HID];         // S = T@W_eembed + deg*b
__device__ float g_G[(size_t)N_PAD * HID];         // send-side gather array (fp32)
__device__ float g_agg[(size_t)N_PAD * HID];
__device__ float g_aggbase[N_LAYERS][(size_t)N_PAD * HID];  // S@M_l, all layers
__device__ int   g_deg[N_PAD];
__device__ float g_Ew[2][16384];                   // E_l chain (fp32, ping-pong)
__device__ float g_dvec[N_LAYERS * HID];           // d_l vectors
__device__ float g_Ph[NUM_GRAPHS * HID];           // pooled h3
__device__ float g_Pa[NUM_GRAPHS * HID];           // pooled agg3
__device__ int   g_cnt[NUM_GRAPHS];                // nodes per graph
// 37 weight slots (fp16 padded [n][k] images): 0=W_embed; layer base=1+9l:
// +0 Wm_s +1 Wm_r +2 Wm_e +3 We_s +4 We_r +5 We_e +6 Wh_a +7 Wh_b +8 M_l
__device__ uint4 g_Bw[(size_t)37 * 2176];

// ---------------------------------------------------------------------------
// PTX helpers
// ---------------------------------------------------------------------------
__device__ __forceinline__ uint32_t smem_u32(const void* p) {
    uint32_t a;
    asm("{ .reg .u64 t; cvta.to.shared.u64 t, %1; cvt.u32.u64 %0, t; }" : "=r"(a) : "l"(p));
    return a;
}
__device__ __forceinline__ void red_add_v4(float* addr, float a, float b, float c, float d) {
    asm volatile("red.global.add.v4.f32 [%0], {%1, %2, %3, %4};"
                 :: "l"(addr), "f"(a), "f"(b), "f"(c), "f"(d) : "memory");
}
__device__ __forceinline__ void ldsm_x4(uint32_t addr, uint32_t r[4]) {
    asm volatile("ldmatrix.sync.aligned.m8n8.x4.shared.b16 {%0,%1,%2,%3}, [%4];"
                 : "=r"(r[0]), "=r"(r[1]), "=r"(r[2]), "=r"(r[3]) : "r"(addr));
}
__device__ __forceinline__ void mma_f16(float c[4], const uint32_t a[4], uint32_t b0, uint32_t b1) {
    asm volatile("mma.sync.aligned.m16n8k16.row.col.f32.f16.f16.f32 "
                 "{%0,%1,%2,%3}, {%4,%5,%6,%7}, {%8,%9}, {%0,%1,%2,%3};"
                 : "+f"(c[0]), "+f"(c[1]), "+f"(c[2]), "+f"(c[3])
                 : "r"(a[0]), "r"(a[1]), "r"(a[2]), "r"(a[3]), "r"(b0), "r"(b1));
}
__device__ __forceinline__ uint32_t pack_hi_lo(float a, float b, uint32_t& lo_out) {
    __half ha = __float2half_rn(a), hb = __float2half_rn(b);
    float ra = a - __half2float(ha), rb = b - __half2float(hb);
    __half la = __float2half_rn(ra), lb = __float2half_rn(rb);
    lo_out = (uint32_t)__half_as_ushort(la) | ((uint32_t)__half_as_ushort(lb) << 16);
    return (uint32_t)__half_as_ushort(ha) | ((uint32_t)__half_as_ushort(hb) << 16);
}

__device__ __forceinline__ void stage_B(int slot, int tid, char* smem, int off)
{
    const uint4* src = g_Bw + (size_t)slot * 2176;
    uint4* dst = (uint4*)(smem + off);
#pragma unroll
    for (int i = 0; i < 9; i++) {
        int idx = tid + i * 256;
        if (idx < 2176) dst[idx] = src[idx];
    }
}

// ---------------------------------------------------------------------------
// A loaders
// ---------------------------------------------------------------------------
__device__ __forceinline__ void load_A4(const uint4* __restrict__ A, int row0, int ks,
                                        int lane, uint4 av[4])
{
    const uint4* base = A + (size_t)(row0 + (lane >> 2)) * 32 + ks * 4 + (lane & 3);
#pragma unroll
    for (int mi = 0; mi < 2; mi++)
#pragma unroll
        for (int jh = 0; jh < 2; jh++)
            av[mi * 2 + jh] = base[(size_t)(mi * 16 + jh * 8) * 32];
}
template<bool GUARD>
__device__ __forceinline__ void load_A_raw(const float* __restrict__ A, int row0, int k0,
                                           int lane, float2 av[8])
{
    const int r = row0 + (lane >> 2);
    const int c = k0 + (lane & 3) * 2;
#pragma unroll
    for (int mi = 0; mi < 2; mi++)
#pragma unroll
        for (int jh = 0; jh < 2; jh++) {
            int row = r + mi * 16 + jh * 8;
            const float* rp = A + (size_t)row * HID + c;
#pragma unroll
            for (int jc = 0; jc < 2; jc++) {
                float2 v = make_float2(0.f, 0.f);
                if (!GUARD || row < N_NODES) v = *(const float2*)(rp + jc * 8);
                av[mi * 4 + jh + 2 * jc] = v;
            }
        }
}

// ---------------------------------------------------------------------------
// 32-MMA inner block (2-product fp16 emulation)
// ---------------------------------------------------------------------------
__device__ __forceinline__ void mma_block(const uint32_t ah[8], const uint32_t al[8],
                                          uint32_t bBase, uint32_t ko, float acc[2][8][4])
{
#pragma unroll
    for (int nb = 0; nb < 4; nb++) {
        uint32_t bh[4];
        ldsm_x4(bBase + nb * 16 * LDB + ko, bh);
#pragma unroll
        for (int half = 0; half < 2; half++) {
            const int ni = nb * 2 + half;
#pragma unroll
            for (int mi = 0; mi < 2; mi++) {
                mma_f16(acc[mi][ni], &ah[mi * 4], bh[half], bh[half + 2]);
                mma_f16(acc[mi][ni], &al[mi * 4], bh[half], bh[half + 2]);
            }
        }
    }
}

__device__ __forceinline__ void mma_pass_bf(const uint4* __restrict__ A, int m0,
                                            uint32_t sb, int bOff, int wid, int lane,
                                            float acc[2][8][4])
{
    const int wm = wid & 3, wn = wid >> 2;
    const uint32_t lrow = (uint32_t)((lane & 15) * LDB + (lane >> 4) * 16);
    const uint32_t bBase = sb + bOff + wn * 64 * LDB + lrow;
    const int row0 = m0 + wm * 32;

    uint4 av[4];
    load_A4(A, row0, 0, lane, av);
#pragma unroll
    for (int ks = 0; ks < 8; ks++) {
        uint32_t ah[8], al[8];
#pragma unroll
        for (int s = 0; s < 4; s++) {
            const int mi = s >> 1, jh = s & 1;
            ah[mi * 4 + jh]     = av[s].x;
            ah[mi * 4 + jh + 2] = av[s].y;
            al[mi * 4 + jh]     = av[s].z;
            al[mi * 4 + jh + 2] = av[s].w;
        }
        if (ks < 7) load_A4(A, row0, ks + 1, lane, av);
        mma_block(ah, al, bBase, (uint32_t)(ks * 32), acc);
    }
}

template<bool GUARD>
__device__ __forceinline__ void mma_pass_f32(const float* __restrict__ A, int m0,
                                             uint32_t sb, int bOff, int wid, int lane,
                                             float acc[2][8][4])
{
    const int wm = wid & 3, wn = wid >> 2;
    const uint32_t lrow = (uint32_t)((lane & 15) * LDB + (lane >> 4) * 16);
    const uint32_t bBase = sb + bOff + wn * 64 * LDB + lrow;
    const int row0 = m0 + wm * 32;

    float2 av[8];
    load_A_raw<GUARD>(A, row0, 0, lane, av);
#pragma unroll
    for (int ks = 0; ks < 8; ks++) {
        uint32_t ah[8], al[8];
#pragma unroll
        for (int i = 0; i < 8; i++) ah[i] = pack_hi_lo(av[i].x, av[i].y, al[i]);
        if (ks < 7) load_A_raw<GUARD>(A, row0, (ks + 1) * 16, lane, av);
        mma_block(ah, al, bBase, (uint32_t)(ks * 32), acc);
    }
}

__device__ __forceinline__ void zero_acc(float acc[2][8][4]) {
#pragma unroll
    for (int mi = 0; mi < 2; mi++)
#pragma unroll
        for (int ni = 0; ni < 8; ni++)
#pragma unroll
            for (int j = 0; j < 4; j++) acc[mi][ni][j] = 0.f;
}

__device__ __forceinline__ void store_frag_row(uint4* __restrict__ C, int row, int wn, int lane,
                                               const float2 vals[8])
{
    uint4* Cp = C + (size_t)row * 32 + (lane & 3);
#pragma unroll
    for (int ni2 = 0; ni2 < 8; ni2 += 2) {
        uint4 v;
        v.x = pack_hi_lo(vals[ni2].x,     vals[ni2].y,     v.z);
        v.y = pack_hi_lo(vals[ni2 + 1].x, vals[ni2 + 1].y, v.w);
        Cp[(size_t)(wn * 4 + (ni2 >> 1)) * 4] = v;
    }
}

// ---------------------------------------------------------------------------
// Weight prep
// ---------------------------------------------------------------------------
__global__ __launch_bounds__(256)
void prep_weights(const float* __restrict__ W_embed, const float* __restrict__ Wm,
                  const float* __restrict__ Wh, const float* __restrict__ We)
{
    int t = blockIdx.x;
    const float* src;
    int slot;
    if (t == 0) { src = W_embed; slot = 0; }
    else if (t == 33) { src = Wm + 256 * HID; slot = 9; }   // M_0 = Wm_e_0
    else {
        int tt = t - 1, l = tt >> 3, j = tt & 7;
        slot = 1 + l * 9 + j;
        if (j < 3)      src = Wm + (size_t)l * 384 * HID + j * 16384;
        else if (j < 6) src = We + (size_t)l * 384 * HID + (j - 3) * 16384;
        else            src = Wh + (size_t)l * 256 * HID + (j - 6) * 16384;
    }
    char* dst = (char*)(g_Bw + (size_t)slot * 2176);
    for (int i = threadIdx.x; i < 16384; i += 256) {
        int k = i >> 7, n = i & 127;
        *(__half*)(dst + (uint32_t)(n * LDB + k * 2)) = __float2half_rn(src[i]);
    }
}

// Compose: grid (2, 8). x=0: M_l image = fp16(Eold @ Wm_e); x=1: Enew = Eold @ We_e
__global__ __launch_bounds__(256)
void compose_kernel(const float* __restrict__ Eold, const float* __restrict__ Wm_e,
                    const float* __restrict__ We_e, uint4* __restrict__ slotimg,
                    float* __restrict__ Enew)
{
    const float* B = blockIdx.x ? We_e : Wm_e;
    const int i = blockIdx.y * 16 + (threadIdx.x >> 4);
    const int j0 = (threadIdx.x & 15) * 8;
    float acc[8];
#pragma unroll
    for (int j = 0; j < 8; j++) acc[j] = 0.f;
    for (int k = 0; k < 128; k++) {
        float a = Eold[i * 128 + k];
        const float* br = B + k * 128 + j0;
#pragma unroll
        for (int j = 0; j < 8; j++) acc[j] += a * br[j];
    }
    if (blockIdx.x == 0) {
        char* dst = (char*)slotimg;
#pragma unroll
        for (int j = 0; j < 8; j++)
            *(__half*)(dst + (uint32_t)((j0 + j) * LDB + i * 2)) = __float2half_rn(acc[j]);
    } else {
#pragma unroll
        for (int j = 0; j < 8; j++) Enew[i * 128 + j0 + j] = acc[j];
    }
}

// c/d chain: d_l = bm_l + c_l@Wm_e_l ; c_{l+1} = c_l@We_e_l + be_l
__global__ __launch_bounds__(128)
void dc_kernel(const float* __restrict__ bm, const float* __restrict__ Wm,
               const float* __restrict__ be, const float* __restrict__ We)
{
    __shared__ float c[128], cn[128];
    const int j = threadIdx.x;
    c[j] = 0.f;
    __syncthreads();
    for (int l = 0; l < N_LAYERS; l++) {
        const float* Wme = Wm + (size_t)l * 49152 + 32768;
        const float* Wee = We + (size_t)l * 49152 + 32768;
        float dj = bm[l * 128 + j], cj = be[l * 128 + j];
        for (int k = 0; k < 128; k++) {
            dj += c[k] * Wme[k * 128 + j];
            cj += c[k] * Wee[k * 128 + j];
        }
        g_dvec[l * 128 + j] = dj;
        cn[j] = cj;
        __syncthreads();
        c[j] = cn[j];
        __syncthreads();
    }
}

// Scatter raw edge features + degree count: T[rec,:] += e_in[e,:]; deg[rec]++
__global__ __launch_bounds__(256)
void scatter_T(const float* __restrict__ e_in, const int* __restrict__ rec,
               float* __restrict__ T)
{
    int gid = blockIdx.x * 256 + threadIdx.x;
    const int total = N_EDGES * 4;
    for (int i = gid; i < total; i += gridDim.x * 256) {
        int e = i >> 2, p = (i & 3) * 4;
        int r = rec[e];
        float4 v = *(const float4*)(e_in + (size_t)e * 16 + p);
        red_add_v4(T + (size_t)r * 16 + p, v.x, v.y, v.z, v.w);
        if ((i & 3) == 0) atomicAdd(&g_deg[r], 1);
    }
}

// S = T @ W_eembed + deg * b_eembed
__global__ __launch_bounds__(128)
void s_gemm(const float* __restrict__ T, const float* __restrict__ W,
            const float* __restrict__ b, float* __restrict__ S)
{
    __shared__ float Ws[16 * 128];
    __shared__ float bs[128];
    for (int i = threadIdx.x; i < 16 * 128; i += blockDim.x) Ws[i] = W[i];
    if (threadIdx.x < 128) bs[threadIdx.x] = b[threadIdx.x];
    __syncthreads();
    const int c = threadIdx.x;
    for (int n = blockIdx.x; n < N_PAD; n += gridDim.x) {
        const float* tr = T + (size_t)n * 16;
        float acc = (float)g_deg[n] * bs[c];
#pragma unroll
        for (int j = 0; j < 16; j++) acc += tr[j] * Ws[j * 128 + c];
        S[(size_t)n * HID + c] = acc;
    }
}

// ---------------------------------------------------------------------------
// smfour: grid (4, GY). aggbase[y] = S @ M_y for all layers in one launch.
// ---------------------------------------------------------------------------
__global__ __launch_bounds__(GT, 2)
void smfour(const float* __restrict__ S)
{
    extern __shared__ char smem[];
    uint32_t sb = smem_u32(smem);
    const int tid = threadIdx.x, wid = tid >> 5, lane = tid & 31;
    const int y = blockIdx.x;
    const int wm = wid & 3, wn = wid >> 2;
    const int r4 = lane >> 2, c2 = (lane & 3) * 2;
    float* outp = g_aggbase[y];

    stage_B(1 + y * 9 + 8, tid, smem, 0);
    __syncthreads();

    for (int m0 = blockIdx.y * 128; m0 < N_PAD; m0 += gridDim.y * 128) {
        float acc[2][8][4];
        zero_acc(acc);
        mma_pass_f32<false>(S, m0, sb, 0, wid, lane, acc);

#pragma unroll
        for (int mi = 0; mi < 2; mi++) {
#pragma unroll
            for (int jh = 0; jh < 2; jh++) {
                int row = m0 + wm * 32 + mi * 16 + jh * 8 + r4;
                float* Cp = outp + (size_t)row * HID;
#pragma unroll
                for (int ni = 0; ni < 8; ni++) {
                    int col = wn * 64 + ni * 8 + c2;
                    *(float2*)(Cp + col) = make_float2(acc[mi][ni][jh * 2 + 0],
                                                       acc[mi][ni][jh * 2 + 1]);
                }
            }
        }
    }
}

// ---------------------------------------------------------------------------
// gh_uv: grid (nY, GY).
//  y=0: G    = h@Wm_s (+ u@Wm_e)
//  y=1: agg  = aggbase_l + deg*(h@Wm_r (+ v@Wm_e) + d_l)
//  y=2: u'   = h@We_s (+ u@We_e)
//  y=3: v'   = h@We_r (+ v@We_e)
// ---------------------------------------------------------------------------
__global__ __launch_bounds__(GT, 2)
void gh_uv(const uint4* __restrict__ h, const uint4* __restrict__ u,
           const uint4* __restrict__ v, int sbase, int hasUV,
           const float* __restrict__ dvec, const float* __restrict__ base,
           float* __restrict__ G, float* __restrict__ agg,
           uint4* __restrict__ uout, uint4* __restrict__ vout)
{
    extern __shared__ char smem[];
    uint32_t sb = smem_u32(smem);
    const int tid = threadIdx.x, wid = tid >> 5, lane = tid & 31;
    const int y = blockIdx.x;
    const int wm = wid & 3, wn = wid >> 2;
    const int r4 = lane >> 2, c2 = (lane & 3) * 2;
    const uint4* A2 = (y & 1) ? v : u;

    static const int slot1_of[4] = {0, 1, 3, 4};
    stage_B(sbase + slot1_of[y], tid, smem, 0);
    if (hasUV) stage_B(sbase + ((y < 2) ? 2 : 5), tid, smem, TILE_BYTES);
    __syncthreads();

    for (int m0 = blockIdx.y * 128; m0 < N_PAD; m0 += gridDim.y * 128) {
        float acc[2][8][4];
        zero_acc(acc);
        mma_pass_bf(h, m0, sb, 0, wid, lane, acc);
        if (hasUV) mma_pass_bf(A2, m0, sb, TILE_BYTES, wid, lane, acc);

        if (y == 1) {
#pragma unroll
            for (int mi = 0; mi < 2; mi++) {
#pragma unroll
                for (int jh = 0; jh < 2; jh++) {
                    int row = m0 + wm * 32 + mi * 16 + jh * 8 + r4;
                    float d = (float)g_deg[row];
                    const float* Bp = base + (size_t)row * HID;
                    float* Cp = agg + (size_t)row * HID;
#pragma unroll
                    for (int ni = 0; ni < 8; ni++) {
                        int col = wn * 64 + ni * 8 + c2;
                        float2 b = *(const float2*)(dvec + col);
                        float2 o = *(const float2*)(Bp + col);
                        *(float2*)(Cp + col) = make_float2(
                            o.x + d * (acc[mi][ni][jh * 2 + 0] + b.x),
                            o.y + d * (acc[mi][ni][jh * 2 + 1] + b.y));
                    }
                }
            }
        } else if (y == 0) {
#pragma unroll
            for (int mi = 0; mi < 2; mi++) {
#pragma unroll
                for (int jh = 0; jh < 2; jh++) {
                    int row = m0 + wm * 32 + mi * 16 + jh * 8 + r4;
                    float* Cp = G + (size_t)row * HID;
#pragma unroll
                    for (int ni = 0; ni < 8; ni++) {
                        int col = wn * 64 + ni * 8 + c2;
                        *(float2*)(Cp + col) = make_float2(acc[mi][ni][jh * 2 + 0],
                                                           acc[mi][ni][jh * 2 + 1]);
                    }
                }
            }
        } else {
            uint4* C = (y == 2) ? uout : vout;
#pragma unroll
            for (int mi = 0; mi < 2; mi++) {
#pragma unroll
                for (int jh = 0; jh < 2; jh++) {
                    int row = m0 + wm * 32 + mi * 16 + jh * 8 + r4;
                    float2 vals[8];
#pragma unroll
                    for (int ni = 0; ni < 8; ni++) {
                        vals[ni] = make_float2(acc[mi][ni][jh * 2 + 0],
                                               acc[mi][ni][jh * 2 + 1]);
                    }
                    store_frag_row(C, row, wn, lane, vals);
                }
            }
        }
    }
}

// ---------------------------------------------------------------------------
// scatter_G: agg[rec[e], :] += G[send[e], :]
// ---------------------------------------------------------------------------
__global__ __launch_bounds__(256)
void scatter_G(const float* __restrict__ G, const int* __restrict__ send,
               const int* __restrict__ rec, float* __restrict__ agg)
{
    const int w = (blockIdx.x * 256 + threadIdx.x) >> 5;
    const int lane = threadIdx.x & 31;
    const int nwarp = gridDim.x * 8;
    for (int e = w; e < N_EDGES; e += nwarp) {
        int s = send[e], r = rec[e];
        float4 v = *(const float4*)(G + (size_t)s * HID + lane * 4);
        red_add_v4(agg + (size_t)r * HID + lane * 4, v.x, v.y, v.z, v.w);
    }
}

// ---------------------------------------------------------------------------
// embed_gemm: C_frag = h_in(fp32, guarded) @ B0 + bias
// ---------------------------------------------------------------------------
__global__ __launch_bounds__(GT, 2)
void embed_gemm(const float* __restrict__ A, int slot,
                const float* __restrict__ bias, uint4* __restrict__ C)
{
    extern __shared__ char smem[];
    uint32_t sb = smem_u32(smem);
    const int tid = threadIdx.x, wid = tid >> 5, lane = tid & 31;
    const int wm = wid & 3, wn = wid >> 2;
    const int r4 = lane >> 2, c2 = (lane & 3) * 2;

    stage_B(slot, tid, smem, 0);
    __syncthreads();

    for (int m0 = blockIdx.x * 128; m0 < N_PAD; m0 += gridDim.x * 128) {
        float acc[2][8][4];
        zero_acc(acc);
        mma_pass_f32<true>(A, m0, sb, 0, wid, lane, acc);

#pragma unroll
        for (int mi = 0; mi < 2; mi++) {
#pragma unroll
            for (int jh = 0; jh < 2; jh++) {
                int row = m0 + wm * 32 + mi * 16 + jh * 8 + r4;
                float2 vals[8];
#pragma unroll
                for (int ni = 0; ni < 8; ni++) {
                    int col = wn * 64 + ni * 8 + c2;
                    float2 b = *(const float2*)(bias + col);
                    vals[ni] = make_float2(acc[mi][ni][jh * 2 + 0] + b.x,
                                           acc[mi][ni][jh * 2 + 1] + b.y);
                }
                store_frag_row(C, row, wn, lane, vals);
            }
        }
    }
}

// ---------------------------------------------------------------------------
// hnew_gemm: C_frag = h@Wh_a + agg(fp32)@Wh_b + bias
// ---------------------------------------------------------------------------
__global__ __launch_bounds__(GT, 2)
void hnew_gemm(const uint4* __restrict__ A1, int slot1,
               const float* __restrict__ A2, int slot2,
               const float* __restrict__ bias, uint4* __restrict__ C)
{
    extern __shared__ char smem[];
    uint32_t sb = smem_u32(smem);
    const int tid = threadIdx.x, wid = tid >> 5, lane = tid & 31;
    const int wm = wid & 3, wn = wid >> 2;
    const int r4 = lane >> 2, c2 = (lane & 3) * 2;

    stage_B(slot1, tid, smem, 0);
    stage_B(slot2, tid, smem, TILE_BYTES);
    __syncthreads();

    for (int m0 = blockIdx.x * 128; m0 < N_PAD; m0 += gridDim.x * 128) {
        float acc[2][8][4];
        zero_acc(acc);
        mma_pass_bf(A1, m0, sb, 0, wid, lane, acc);
        mma_pass_f32<false>(A2, m0, sb, TILE_BYTES, wid, lane, acc);

#pragma unroll
        for (int mi = 0; mi < 2; mi++) {
#pragma unroll
            for (int jh = 0; jh < 2; jh++) {
                int row = m0 + wm * 32 + mi * 16 + jh * 8 + r4;
                float2 vals[8];
#pragma unroll
                for (int ni = 0; ni < 8; ni++) {
                    int col = wn * 64 + ni * 8 + c2;
                    float2 b = *(const float2*)(bias + col);
                    vals[ni] = make_float2(acc[mi][ni][jh * 2 + 0] + b.x,
                                           acc[mi][ni][jh * 2 + 1] + b.y);
                }
                store_frag_row(C, row, wn, lane, vals);
            }
        }
    }
}

// ---------------------------------------------------------------------------
// Pool h3 (frag layout) -> Ph; also counts nodes per graph (c==0).
// ---------------------------------------------------------------------------
__global__ __launch_bounds__(128)
void pool_h(const uint4* __restrict__ h, const int* __restrict__ batch,
            float* __restrict__ Ph)
{
    const int n0 = blockIdx.x * 128;
    const int c = threadIdx.x;
    const int cp = c >> 1;
    const int qidx = (cp >> 3) * 4 + (cp & 3);
    const int pos = (cp >> 2) & 1;
    const uint32_t sh = (c & 1) ? 16 : 0;

    int curg = batch[n0];
    float sum = 0.f;
    int cnt = 0;
    for (int i = 0; i < 128; i++) {
        int n = n0 + i;
        if (n >= N_NODES) break;
        int g = batch[n];
        if (g != curg) {
            atomicAdd(&Ph[(size_t)curg * HID + c], sum);
            if (c == 0) atomicAdd(&g_cnt[curg], cnt);
            sum = 0.f; cnt = 0;
            curg = g;
        }
        uint4 v = h[(size_t)n * 32 + qidx];
        uint32_t uh = pos ? v.y : v.x;
        uint32_t ul = pos ? v.w : v.z;
        float hi = __half2float(__ushort_as_half((unsigned short)((uh >> sh) & 0xFFFF)));
        float lo = __half2float(__ushort_as_half((unsigned short)((ul >> sh) & 0xFFFF)));
        sum += hi + lo;
        cnt++;
    }
    atomicAdd(&Ph[(size_t)curg * HID + c], sum);
    if (c == 0) atomicAdd(&g_cnt[curg], cnt);
}

// Pool agg3 (fp32) -> Pa.
__global__ __launch_bounds__(128)
void pool_a(const float* __restrict__ agg, const int* __restrict__ batch,
            float* __restrict__ Pa)
{
    const int n0 = blockIdx.x * 128;
    const int c = threadIdx.x;
    int curg = batch[n0];
    float sum = 0.f;
    for (int i = 0; i < 128; i++) {
        int n = n0 + i;
        if (n >= N_NODES) break;
        int g = batch[n];
        if (g != curg) {
            atomicAdd(&Pa[(size_t)curg * HID + c], sum);
            sum = 0.f;
            curg = g;
        }
        sum += agg[(size_t)n * HID + c];
    }
    atomicAdd(&Pa[(size_t)curg * HID + c], sum);
}

// out[g,:] = Ph[g,:]@Wh_a + Pa[g,:]@Wh_b + cnt[g]*bh   (fp32, layer 3 weights)
__global__ __launch_bounds__(128)
void out_gemm(const float* __restrict__ Ph, const float* __restrict__ Pa,
              const float* __restrict__ Wh3, const float* __restrict__ bh3,
              float* __restrict__ out)
{
    __shared__ float ph[128], pa[128];
    const int g = blockIdx.x;
    const int c = threadIdx.x;
    ph[c] = Ph[(size_t)g * HID + c];
    pa[c] = Pa[(size_t)g * HID + c];
    __syncthreads();
    float acc = (float)g_cnt[g] * bh3[c];
    const float* Wa = Wh3;               // [0:128) rows
    const float* Wb = Wh3 + 128 * HID;   // [128:256) rows
    for (int k = 0; k < 128; k++) {
        acc += ph[k] * Wa[k * HID + c];
        acc += pa[k] * Wb[k * HID + c];
    }
    out[(size_t)g * HID + c] = acc;
}

// ---------------------------------------------------------------------------
// Launch
// ---------------------------------------------------------------------------
extern "C" void kernel_launch(void* const* d_in, const int* in_sizes, int n_in,
                              void* d_out, int out_size)
{
    const float* h_in     = (const float*)d_in[0];
    const float* e_in     = (const float*)d_in[1];
    const int*   edge_idx = (const int*)  d_in[2];
    const int*   batch    = (const int*)  d_in[3];
    const float* W_embed  = (const float*)d_in[4];
    const float* b_embed  = (const float*)d_in[5];
    const float* W_eembed = (const float*)d_in[6];
    const float* b_eembed = (const float*)d_in[7];
    const float* Wm       = (const float*)d_in[8];
    const float* bm       = (const float*)d_in[9];
    const float* Wh       = (const float*)d_in[10];
    const float* bh       = (const float*)d_in[11];
    const float* We       = (const float*)d_in[12];
    const float* be       = (const float*)d_in[13];
    float*       out      = (float*)d_out;

    cudaFuncSetAttribute(gh_uv,      cudaFuncAttributeMaxDynamicSharedMemorySize, SMEM_2);
    cudaFuncSetAttribute(hnew_gemm,  cudaFuncAttributeMaxDynamicSharedMemorySize, SMEM_2);
    cudaFuncSetAttribute(embed_gemm, cudaFuncAttributeMaxDynamicSharedMemorySize, SMEM_1);
    cudaFuncSetAttribute(smfour,     cudaFuncAttributeMaxDynamicSharedMemorySize, SMEM_1);

    uint4 *hbuf, *uvbuf, *bw;
    float *Tp, *Sp, *Gp, *aggp, *Ew, *dvecp, *Php, *Pap;
    int *degp, *cntp;
    cudaGetSymbolAddress((void**)&hbuf, g_hbf);
    cudaGetSymbolAddress((void**)&uvbuf, g_uv);
    cudaGetSymbolAddress((void**)&Tp,   g_T);
    cudaGetSymbolAddress((void**)&Sp,   g_S);
    cudaGetSymbolAddress((void**)&Gp,   g_G);
    cudaGetSymbolAddress((void**)&aggp, g_agg);
    cudaGetSymbolAddress((void**)&degp, g_deg);
    cudaGetSymbolAddress((void**)&Ew,   g_Ew);
    cudaGetSymbolAddress((void**)&bw,   g_Bw);
    cudaGetSymbolAddress((void**)&dvecp, g_dvec);
    cudaGetSymbolAddress((void**)&Php,  g_Ph);
    cudaGetSymbolAddress((void**)&Pap,  g_Pa);
    cudaGetSymbolAddress((void**)&cntp, g_cnt);
    float* basep;
    cudaGetSymbolAddress((void**)&basep, g_aggbase);

    uint4* hb[2] = { hbuf, hbuf + (size_t)N_PAD * 32 };
    uint4* ub[2] = { uvbuf, uvbuf + (size_t)N_PAD * 32 };
    uint4* vb[2] = { uvbuf + 2 * (size_t)N_PAD * 32, uvbuf + 3 * (size_t)N_PAD * 32 };
    float* Eb[2] = { Ew, Ew + 16384 };
    const int* send = edge_idx;
    const int* rec  = edge_idx + N_EDGES;

    // Prep
    cudaMemsetAsync(degp, 0, N_PAD * sizeof(int));
    cudaMemsetAsync(Tp, 0, (size_t)N_PAD * 16 * sizeof(float));
    scatter_T<<<4096, 256>>>(e_in, rec, Tp);
    prep_weights<<<34, 256>>>(W_embed, Wm, Wh, We);
    // E-chain: first compose reads We_e_0 directly
    int esrc = 0;
    for (int l = 1; l < N_LAYERS; l++) {
        const float* Eold = (l == 1) ? (We + 256 * HID) : Eb[esrc];
        compose_kernel<<<dim3(2, 8), 256>>>(
            Eold,
            Wm + (size_t)l * 49152 + 32768,
            We + (size_t)l * 49152 + 32768,
            bw + (size_t)(1 + l * 9 + 8) * 2176,
            Eb[1 - esrc]);
        if (l > 1) esrc = 1 - esrc;
        else esrc = 1;
    }
    dc_kernel<<<1, 128>>>(bm, Wm, be, We);
    s_gemm<<<2048, 128>>>(Tp, W_eembed, b_eembed, Sp);
    embed_gemm<<<296, GT, SMEM_1>>>(h_in, 0, b_embed, hb[0]);
    smfour<<<dim3(4, 148), GT, SMEM_1>>>(Sp);

    int cur = 0, uvcur = 0;
    for (int l = 0; l < N_LAYERS; l++) {
        int sbase = 1 + l * 9;
        int hasUV = (l > 0) ? 1 : 0;
        int nY = (l < N_LAYERS - 1) ? 4 : 2;
        uint4* hcur = hb[cur];
        uint4* hnxt = hb[1 - cur];

        // G / agg / u' / v' in one launch
        gh_uv<<<dim3(nY, 148), GT, SMEM_2>>>(
            hcur, ub[uvcur], vb[uvcur], sbase, hasUV, dvecp + l * HID,
            basep + (size_t)l * N_PAD * HID, Gp, aggp,
            ub[1 - uvcur], vb[1 - uvcur]);
        if (l < N_LAYERS - 1) uvcur = 1 - uvcur;

        // agg[r] += G[s] over edges
        scatter_G<<<2048, 256>>>(Gp, send, rec, aggp);

        if (l < N_LAYERS - 1) {
            // h' = h@Wh_a + agg@Wh_b + bh
            hnew_gemm<<<296, GT, SMEM_2>>>(hcur, sbase + 6, aggp, sbase + 7,
                                           bh + (size_t)l * HID, hnxt);
            cur = 1 - cur;
        }
    }

    // Final: out = pool(h3)@Wh_a3 + pool(agg3)@Wh_b3 + cnt*bh3
    cudaMemsetAsync(Php, 0, NUM_GRAPHS * HID * sizeof(float));
    cudaMemsetAsync(Pap, 0, NUM_GRAPHS * HID * sizeof(float));
    cudaMemsetAsync(cntp, 0, NUM_GRAPHS * sizeof(int));
    pool_h<<<313, 128>>>(hb[cur], batch, Php);
    pool_a<<<313, 128>>>(aggp, batch, Pap);
    out_gemm<<<NUM_GRAPHS, 128>>>(Php, Pap,
                                  Wh + (size_t)3 * 256 * HID, bh + (size_t)3 * HID, out);
}

// round 16
// speedup vs baseline: 1.4104x; 1.4104x over previous
#include <cuda_runtime.h>
#include <cuda_fp16.h>
#include <cstdint>

#define N_NODES 40000
#define N_PAD   40064   // 313 * 128
#define N_EDGES 640000
#define HID 128
#define N_LAYERS 4
#define NUM_GRAPHS 256

#define GT 256          // 8 warps per GEMM CTA

#define LDB 272
#define TILE_BYTES 34816
#define SMEM_1 34816
#define SMEM_2 69632

// ---------------------------------------------------------------------------
// Scratch
// ---------------------------------------------------------------------------
__device__ uint4 g_hbf[2][(size_t)N_PAD * 32];
__device__ uint4 g_uv[4][(size_t)N_PAD * 32];      // u0,u1,v0,v1 ping-pong
__device__ float g_T[(size_t)N_PAD * 16];          // scattered raw edge feats
__device__ float g_S[(size_t)N_PAD * HID];         // S = T@W_eembed + deg*b
__device__ float g_G[(size_t)N_PAD * HID];         // send-side gather array (fp32)
__device__ float g_agg[(size_t)N_PAD * HID];
__device__ float g_aggbase[N_LAYERS][(size_t)N_PAD * HID];  // S@M_l
__device__ int   g_deg[N_PAD];
__device__ float g_Ew[2][16384];                   // E_l chain (fp32, ping-pong)
__device__ float g_dvec[N_LAYERS * HID];           // d_l vectors
__device__ float g_Ph[NUM_GRAPHS * HID];           // pooled h3
__device__ float g_Pa[NUM_GRAPHS * HID];           // pooled agg3
__device__ int   g_cnt[NUM_GRAPHS];                // nodes per graph
// 37 weight slots (fp16 padded [n][k] images): 0=W_embed; layer base=1+9l:
// +0 Wm_s +1 Wm_r +2 Wm_e +3 We_s +4 We_r +5 We_e +6 Wh_a +7 Wh_b +8 M_l
__device__ uint4 g_Bw[(size_t)37 * 2176];

// ---------------------------------------------------------------------------
// PTX helpers
// ---------------------------------------------------------------------------
__device__ __forceinline__ uint32_t smem_u32(const void* p) {
    uint32_t a;
    asm("{ .reg .u64 t; cvta.to.shared.u64 t, %1; cvt.u32.u64 %0, t; }" : "=r"(a) : "l"(p));
    return a;
}
__device__ __forceinline__ void red_add_v4(float* addr, float a, float b, float c, float d) {
    asm volatile("red.global.add.v4.f32 [%0], {%1, %2, %3, %4};"
                 :: "l"(addr), "f"(a), "f"(b), "f"(c), "f"(d) : "memory");
}
__device__ __forceinline__ void ldsm_x4(uint32_t addr, uint32_t r[4]) {
    asm volatile("ldmatrix.sync.aligned.m8n8.x4.shared.b16 {%0,%1,%2,%3}, [%4];"
                 : "=r"(r[0]), "=r"(r[1]), "=r"(r[2]), "=r"(r[3]) : "r"(addr));
}
__device__ __forceinline__ void mma_f16(float c[4], const uint32_t a[4], uint32_t b0, uint32_t b1) {
    asm volatile("mma.sync.aligned.m16n8k16.row.col.f32.f16.f16.f32 "
                 "{%0,%1,%2,%3}, {%4,%5,%6,%7}, {%8,%9}, {%0,%1,%2,%3};"
                 : "+f"(c[0]), "+f"(c[1]), "+f"(c[2]), "+f"(c[3])
                 : "r"(a[0]), "r"(a[1]), "r"(a[2]), "r"(a[3]), "r"(b0), "r"(b1));
}
__device__ __forceinline__ uint32_t pack_hi_lo(float a, float b, uint32_t& lo_out) {
    __half ha = __float2half_rn(a), hb = __float2half_rn(b);
    float ra = a - __half2float(ha), rb = b - __half2float(hb);
    __half la = __float2half_rn(ra), lb = __float2half_rn(rb);
    lo_out = (uint32_t)__half_as_ushort(la) | ((uint32_t)__half_as_ushort(lb) << 16);
    return (uint32_t)__half_as_ushort(ha) | ((uint32_t)__half_as_ushort(hb) << 16);
}

__device__ __forceinline__ void stage_B(int slot, int tid, char* smem, int off)
{
    const uint4* src = g_Bw + (size_t)slot * 2176;
    uint4* dst = (uint4*)(smem + off);
#pragma unroll
    for (int i = 0; i < 9; i++) {
        int idx = tid + i * 256;
        if (idx < 2176) dst[idx] = src[idx];
    }
}

// ---------------------------------------------------------------------------
// A loaders
// ---------------------------------------------------------------------------
__device__ __forceinline__ void load_A4(const uint4* __restrict__ A, int row0, int ks,
                                        int lane, uint4 av[4])
{
    const uint4* base = A + (size_t)(row0 + (lane >> 2)) * 32 + ks * 4 + (lane & 3);
#pragma unroll
    for (int mi = 0; mi < 2; mi++)
#pragma unroll
        for (int jh = 0; jh < 2; jh++)
            av[mi * 2 + jh] = base[(size_t)(mi * 16 + jh * 8) * 32];
}
template<bool GUARD>
__device__ __forceinline__ void load_A_raw(const float* __restrict__ A, int row0, int k0,
                                           int lane, float2 av[8])
{
    const int r = row0 + (lane >> 2);
    const int c = k0 + (lane & 3) * 2;
#pragma unroll
    for (int mi = 0; mi < 2; mi++)
#pragma unroll
        for (int jh = 0; jh < 2; jh++) {
            int row = r + mi * 16 + jh * 8;
            const float* rp = A + (size_t)row * HID + c;
#pragma unroll
            for (int jc = 0; jc < 2; jc++) {
                float2 v = make_float2(0.f, 0.f);
                if (!GUARD || row < N_NODES) v = *(const float2*)(rp + jc * 8);
                av[mi * 4 + jh + 2 * jc] = v;
            }
        }
}

// ---------------------------------------------------------------------------
// 32-MMA inner block (2-product fp16 emulation)
// ---------------------------------------------------------------------------
__device__ __forceinline__ void mma_block(const uint32_t ah[8], const uint32_t al[8],
                                          uint32_t bBase, uint32_t ko, float acc[2][8][4])
{
#pragma unroll
    for (int nb = 0; nb < 4; nb++) {
        uint32_t bh[4];
        ldsm_x4(bBase + nb * 16 * LDB + ko, bh);
#pragma unroll
        for (int half = 0; half < 2; half++) {
            const int ni = nb * 2 + half;
#pragma unroll
            for (int mi = 0; mi < 2; mi++) {
                mma_f16(acc[mi][ni], &ah[mi * 4], bh[half], bh[half + 2]);
                mma_f16(acc[mi][ni], &al[mi * 4], bh[half], bh[half + 2]);
            }
        }
    }
}

__device__ __forceinline__ void mma_pass_bf(const uint4* __restrict__ A, int m0,
                                            uint32_t sb, int bOff, int wid, int lane,
                                            float acc[2][8][4])
{
    const int wm = wid & 3, wn = wid >> 2;
    const uint32_t lrow = (uint32_t)((lane & 15) * LDB + (lane >> 4) * 16);
    const uint32_t bBase = sb + bOff + wn * 64 * LDB + lrow;
    const int row0 = m0 + wm * 32;

    uint4 av[4];
    load_A4(A, row0, 0, lane, av);
#pragma unroll
    for (int ks = 0; ks < 8; ks++) {
        uint32_t ah[8], al[8];
#pragma unroll
        for (int s = 0; s < 4; s++) {
            const int mi = s >> 1, jh = s & 1;
            ah[mi * 4 + jh]     = av[s].x;
            ah[mi * 4 + jh + 2] = av[s].y;
            al[mi * 4 + jh]     = av[s].z;
            al[mi * 4 + jh + 2] = av[s].w;
        }
        if (ks < 7) load_A4(A, row0, ks + 1, lane, av);
        mma_block(ah, al, bBase, (uint32_t)(ks * 32), acc);
    }
}

template<bool GUARD>
__device__ __forceinline__ void mma_pass_f32(const float* __restrict__ A, int m0,
                                             uint32_t sb, int bOff, int wid, int lane,
                                             float acc[2][8][4])
{
    const int wm = wid & 3, wn = wid >> 2;
    const uint32_t lrow = (uint32_t)((lane & 15) * LDB + (lane >> 4) * 16);
    const uint32_t bBase = sb + bOff + wn * 64 * LDB + lrow;
    const int row0 = m0 + wm * 32;

    float2 av[8];
    load_A_raw<GUARD>(A, row0, 0, lane, av);
#pragma unroll
    for (int ks = 0; ks < 8; ks++) {
        uint32_t ah[8], al[8];
#pragma unroll
        for (int i = 0; i < 8; i++) ah[i] = pack_hi_lo(av[i].x, av[i].y, al[i]);
        if (ks < 7) load_A_raw<GUARD>(A, row0, (ks + 1) * 16, lane, av);
        mma_block(ah, al, bBase, (uint32_t)(ks * 32), acc);
    }
}

__device__ __forceinline__ void zero_acc(float acc[2][8][4]) {
#pragma unroll
    for (int mi = 0; mi < 2; mi++)
#pragma unroll
        for (int ni = 0; ni < 8; ni++)
#pragma unroll
            for (int j = 0; j < 4; j++) acc[mi][ni][j] = 0.f;
}

__device__ __forceinline__ void store_frag_row(uint4* __restrict__ C, int row, int wn, int lane,
                                               const float2 vals[8])
{
    uint4* Cp = C + (size_t)row * 32 + (lane & 3);
#pragma unroll
    for (int ni2 = 0; ni2 < 8; ni2 += 2) {
        uint4 v;
        v.x = pack_hi_lo(vals[ni2].x,     vals[ni2].y,     v.z);
        v.y = pack_hi_lo(vals[ni2 + 1].x, vals[ni2 + 1].y, v.w);
        Cp[(size_t)(wn * 4 + (ni2 >> 1)) * 4] = v;
    }
}

// ---------------------------------------------------------------------------
// Weight prep
// ---------------------------------------------------------------------------
__global__ __launch_bounds__(256)
void prep_weights(const float* __restrict__ W_embed, const float* __restrict__ Wm,
                  const float* __restrict__ Wh, const float* __restrict__ We)
{
    int t = blockIdx.x;
    const float* src;
    int slot;
    if (t == 0) { src = W_embed; slot = 0; }
    else if (t == 33) { src = Wm + 256 * HID; slot = 9; }   // M_0 = Wm_e_0
    else {
        int tt = t - 1, l = tt >> 3, j = tt & 7;
        slot = 1 + l * 9 + j;
        if (j < 3)      src = Wm + (size_t)l * 384 * HID + j * 16384;
        else if (j < 6) src = We + (size_t)l * 384 * HID + (j - 3) * 16384;
        else            src = Wh + (size_t)l * 256 * HID + (j - 6) * 16384;
    }
    char* dst = (char*)(g_Bw + (size_t)slot * 2176);
    for (int i = threadIdx.x; i < 16384; i += 256) {
        int k = i >> 7, n = i & 127;
        *(__half*)(dst + (uint32_t)(n * LDB + k * 2)) = __float2half_rn(src[i]);
    }
}

// Compose: grid (2, 8). x=0: M_l image = fp16(Eold @ Wm_e); x=1: Enew = Eold @ We_e
__global__ __launch_bounds__(256)
void compose_kernel(const float* __restrict__ Eold, const float* __restrict__ Wm_e,
                    const float* __restrict__ We_e, uint4* __restrict__ slotimg,
                    float* __restrict__ Enew)
{
    const float* B = blockIdx.x ? We_e : Wm_e;
    const int i = blockIdx.y * 16 + (threadIdx.x >> 4);
    const int j0 = (threadIdx.x & 15) * 8;
    float acc[8];
#pragma unroll
    for (int j = 0; j < 8; j++) acc[j] = 0.f;
#pragma unroll 16
    for (int k = 0; k < 128; k++) {
        float a = Eold[i * 128 + k];
        const float* br = B + k * 128 + j0;
#pragma unroll
        for (int j = 0; j < 8; j++) acc[j] += a * br[j];
    }
    if (blockIdx.x == 0) {
        char* dst = (char*)slotimg;
#pragma unroll
        for (int j = 0; j < 8; j++)
            *(__half*)(dst + (uint32_t)((j0 + j) * LDB + i * 2)) = __float2half_rn(acc[j]);
    } else {
#pragma unroll
        for (int j = 0; j < 8; j++) Enew[i * 128 + j0 + j] = acc[j];
    }
}

// c/d chain: d_l = bm_l + c_l@Wm_e_l ; c_{l+1} = c_l@We_e_l + be_l
__global__ __launch_bounds__(128)
void dc_kernel(const float* __restrict__ bm, const float* __restrict__ Wm,
               const float* __restrict__ be, const float* __restrict__ We)
{
    __shared__ float c[128], cn[128];
    const int j = threadIdx.x;
    c[j] = 0.f;
    __syncthreads();
    for (int l = 0; l < N_LAYERS; l++) {
        const float* Wme = Wm + (size_t)l * 49152 + 32768;
        const float* Wee = We + (size_t)l * 49152 + 32768;
        float dj = bm[l * 128 + j], cj = be[l * 128 + j];
#pragma unroll 8
        for (int k = 0; k < 128; k++) {
            dj += c[k] * Wme[k * 128 + j];
            cj += c[k] * Wee[k * 128 + j];
        }
        g_dvec[l * 128 + j] = dj;
        cn[j] = cj;
        __syncthreads();
        c[j] = cn[j];
        __syncthreads();
    }
}

__global__ __launch_bounds__(256)
void count_deg(const int* __restrict__ rec)
{
    int i = blockIdx.x * 256 + threadIdx.x;
    if (i < N_EDGES) atomicAdd(&g_deg[rec[i]], 1);
}

// Scatter raw edge features: T[rec,:] += e_in[e,:]
__global__ __launch_bounds__(256)
void scatter_T(const float* __restrict__ e_in, const int* __restrict__ rec,
               float* __restrict__ T)
{
    int gid = blockIdx.x * 256 + threadIdx.x;
    const int total = N_EDGES * 4;
    for (int i = gid; i < total; i += gridDim.x * 256) {
        int e = i >> 2, p = (i & 3) * 4;
        float4 v = *(const float4*)(e_in + (size_t)e * 16 + p);
        red_add_v4(T + (size_t)rec[e] * 16 + p, v.x, v.y, v.z, v.w);
    }
}

// S = T @ W_eembed + deg * b_eembed
__global__ __launch_bounds__(128)
void s_gemm(const float* __restrict__ T, const float* __restrict__ W,
            const float* __restrict__ b, float* __restrict__ S)
{
    __shared__ float Ws[16 * 128];
    __shared__ float bs[128];
    for (int i = threadIdx.x; i < 16 * 128; i += blockDim.x) Ws[i] = W[i];
    if (threadIdx.x < 128) bs[threadIdx.x] = b[threadIdx.x];
    __syncthreads();
    const int c = threadIdx.x;
    for (int n = blockIdx.x; n < N_PAD; n += gridDim.x) {
        const float* tr = T + (size_t)n * 16;
        float acc = (float)g_deg[n] * bs[c];
#pragma unroll
        for (int j = 0; j < 16; j++) acc += tr[j] * Ws[j * 128 + c];
        S[(size_t)n * HID + c] = acc;
    }
}

// ---------------------------------------------------------------------------
// smfour: grid (4, GY). aggbase[y] = S @ M_y for all layers in one launch.
// ---------------------------------------------------------------------------
__global__ __launch_bounds__(GT, 2)
void smfour(const float* __restrict__ S)
{
    extern __shared__ char smem[];
    uint32_t sb = smem_u32(smem);
    const int tid = threadIdx.x, wid = tid >> 5, lane = tid & 31;
    const int y = blockIdx.x;
    const int wm = wid & 3, wn = wid >> 2;
    const int r4 = lane >> 2, c2 = (lane & 3) * 2;
    float* outp = g_aggbase[y];

    stage_B(1 + y * 9 + 8, tid, smem, 0);
    __syncthreads();

    for (int m0 = blockIdx.y * 128; m0 < N_PAD; m0 += gridDim.y * 128) {
        float acc[2][8][4];
        zero_acc(acc);
        mma_pass_f32<false>(S, m0, sb, 0, wid, lane, acc);

#pragma unroll
        for (int mi = 0; mi < 2; mi++) {
#pragma unroll
            for (int jh = 0; jh < 2; jh++) {
                int row = m0 + wm * 32 + mi * 16 + jh * 8 + r4;
                float* Cp = outp + (size_t)row * HID;
#pragma unroll
                for (int ni = 0; ni < 8; ni++) {
                    int col = wn * 64 + ni * 8 + c2;
                    *(float2*)(Cp + col) = make_float2(acc[mi][ni][jh * 2 + 0],
                                                       acc[mi][ni][jh * 2 + 1]);
                }
            }
        }
    }
}

// ---------------------------------------------------------------------------
// gh_gemm: grid (2, GY).
//  y=0: G   = h@Wm_s (+ u@Wm_e)
//  y=1: agg = aggbase_l + deg*(h@Wm_r (+ v@Wm_e) + d_l)
// ---------------------------------------------------------------------------
__global__ __launch_bounds__(GT, 2)
void gh_gemm(const uint4* __restrict__ h, const uint4* __restrict__ u,
             const uint4* __restrict__ v, int sbase, int hasUV,
             const float* __restrict__ dvec, const float* __restrict__ base,
             float* __restrict__ G, float* __restrict__ agg)
{
    extern __shared__ char smem[];
    uint32_t sb = smem_u32(smem);
    const int tid = threadIdx.x, wid = tid >> 5, lane = tid & 31;
    const int y = blockIdx.x;
    const int wm = wid & 3, wn = wid >> 2;
    const int r4 = lane >> 2, c2 = (lane & 3) * 2;
    const uint4* A2 = y ? v : u;

    stage_B(sbase + (y ? 1 : 0), tid, smem, 0);
    if (hasUV) stage_B(sbase + 2, tid, smem, TILE_BYTES);
    __syncthreads();

    for (int m0 = blockIdx.y * 128; m0 < N_PAD; m0 += gridDim.y * 128) {
        float acc[2][8][4];
        zero_acc(acc);
        mma_pass_bf(h, m0, sb, 0, wid, lane, acc);
        if (hasUV) mma_pass_bf(A2, m0, sb, TILE_BYTES, wid, lane, acc);

        if (y == 1) {
#pragma unroll
            for (int mi = 0; mi < 2; mi++) {
#pragma unroll
                for (int jh = 0; jh < 2; jh++) {
                    int row = m0 + wm * 32 + mi * 16 + jh * 8 + r4;
                    float d = (float)g_deg[row];
                    const float* Bp = base + (size_t)row * HID;
                    float* Cp = agg + (size_t)row * HID;
#pragma unroll
                    for (int ni = 0; ni < 8; ni++) {
                        int col = wn * 64 + ni * 8 + c2;
                        float2 b = *(const float2*)(dvec + col);
                        float2 o = *(const float2*)(Bp + col);
                        *(float2*)(Cp + col) = make_float2(
                            o.x + d * (acc[mi][ni][jh * 2 + 0] + b.x),
                            o.y + d * (acc[mi][ni][jh * 2 + 1] + b.y));
                    }
                }
            }
        } else {
#pragma unroll
            for (int mi = 0; mi < 2; mi++) {
#pragma unroll
                for (int jh = 0; jh < 2; jh++) {
                    int row = m0 + wm * 32 + mi * 16 + jh * 8 + r4;
                    float* Cp = G + (size_t)row * HID;
#pragma unroll
                    for (int ni = 0; ni < 8; ni++) {
                        int col = wn * 64 + ni * 8 + c2;
                        *(float2*)(Cp + col) = make_float2(acc[mi][ni][jh * 2 + 0],
                                                           acc[mi][ni][jh * 2 + 1]);
                    }
                }
            }
        }
    }
}

// ---------------------------------------------------------------------------
// uv_gemm: grid (2, GY). y=0: u' = h@We_s (+ u@We_e); y=1: v' = h@We_r (+ v@We_e)
// ---------------------------------------------------------------------------
__global__ __launch_bounds__(GT, 2)
void uv_gemm(const uint4* __restrict__ h, const uint4* __restrict__ u,
             const uint4* __restrict__ v, int sbase, int hasUV,
             uint4* __restrict__ uout, uint4* __restrict__ vout)
{
    extern __shared__ char smem[];
    uint32_t sb = smem_u32(smem);
    const int tid = threadIdx.x, wid = tid >> 5, lane = tid & 31;
    const int y = blockIdx.x;
    const int wm = wid & 3, wn = wid >> 2;
    const int r4 = lane >> 2, c2 = (lane & 3) * 2;
    const uint4* A2 = y ? v : u;
    uint4* C = y ? vout : uout;

    stage_B(sbase + (y ? 4 : 3), tid, smem, 0);
    if (hasUV) stage_B(sbase + 5, tid, smem, TILE_BYTES);
    __syncthreads();

    for (int m0 = blockIdx.y * 128; m0 < N_PAD; m0 += gridDim.y * 128) {
        float acc[2][8][4];
        zero_acc(acc);
        mma_pass_bf(h, m0, sb, 0, wid, lane, acc);
        if (hasUV) mma_pass_bf(A2, m0, sb, TILE_BYTES, wid, lane, acc);

#pragma unroll
        for (int mi = 0; mi < 2; mi++) {
#pragma unroll
            for (int jh = 0; jh < 2; jh++) {
                int row = m0 + wm * 32 + mi * 16 + jh * 8 + r4;
                float2 vals[8];
#pragma unroll
                for (int ni = 0; ni < 8; ni++) {
                    vals[ni] = make_float2(acc[mi][ni][jh * 2 + 0],
                                           acc[mi][ni][jh * 2 + 1]);
                }
                store_frag_row(C, row, wn, lane, vals);
            }
        }
    }
}

// ---------------------------------------------------------------------------
// scatter_G: agg[rec[e], :] += G[send[e], :]
// ---------------------------------------------------------------------------
__global__ __launch_bounds__(256)
void scatter_G(const float* __restrict__ G, const int* __restrict__ send,
               const int* __restrict__ rec, float* __restrict__ agg)
{
    const int w = (blockIdx.x * 256 + threadIdx.x) >> 5;
    const int lane = threadIdx.x & 31;
    const int nwarp = gridDim.x * 8;
    for (int e = w; e < N_EDGES; e += nwarp) {
        int s = send[e], r = rec[e];
        float4 v = *(const float4*)(G + (size_t)s * HID + lane * 4);
        red_add_v4(agg + (size_t)r * HID + lane * 4, v.x, v.y, v.z, v.w);
    }
}

// ---------------------------------------------------------------------------
// embed_gemm: C_frag = h_in(fp32, guarded) @ B0 + bias
// ---------------------------------------------------------------------------
__global__ __launch_bounds__(GT, 2)
void embed_gemm(const float* __restrict__ A, int slot,
                const float* __restrict__ bias, uint4* __restrict__ C)
{
    extern __shared__ char smem[];
    uint32_t sb = smem_u32(smem);
    const int tid = threadIdx.x, wid = tid >> 5, lane = tid & 31;
    const int wm = wid & 3, wn = wid >> 2;
    const int r4 = lane >> 2, c2 = (lane & 3) * 2;

    stage_B(slot, tid, smem, 0);
    __syncthreads();

    for (int m0 = blockIdx.x * 128; m0 < N_PAD; m0 += gridDim.x * 128) {
        float acc[2][8][4];
        zero_acc(acc);
        mma_pass_f32<true>(A, m0, sb, 0, wid, lane, acc);

#pragma unroll
        for (int mi = 0; mi < 2; mi++) {
#pragma unroll
            for (int jh = 0; jh < 2; jh++) {
                int row = m0 + wm * 32 + mi * 16 + jh * 8 + r4;
                float2 vals[8];
#pragma unroll
                for (int ni = 0; ni < 8; ni++) {
                    int col = wn * 64 + ni * 8 + c2;
                    float2 b = *(const float2*)(bias + col);
                    vals[ni] = make_float2(acc[mi][ni][jh * 2 + 0] + b.x,
                                           acc[mi][ni][jh * 2 + 1] + b.y);
                }
                store_frag_row(C, row, wn, lane, vals);
            }
        }
    }
}

// ---------------------------------------------------------------------------
// hnew_gemm: C_frag = h@Wh_a + agg(fp32)@Wh_b + bias
// ---------------------------------------------------------------------------
__global__ __launch_bounds__(GT, 2)
void hnew_gemm(const uint4* __restrict__ A1, int slot1,
               const float* __restrict__ A2, int slot2,
               const float* __restrict__ bias, uint4* __restrict__ C)
{
    extern __shared__ char smem[];
    uint32_t sb = smem_u32(smem);
    const int tid = threadIdx.x, wid = tid >> 5, lane = tid & 31;
    const int wm = wid & 3, wn = wid >> 2;
    const int r4 = lane >> 2, c2 = (lane & 3) * 2;

    stage_B(slot1, tid, smem, 0);
    stage_B(slot2, tid, smem, TILE_BYTES);
    __syncthreads();

    for (int m0 = blockIdx.x * 128; m0 < N_PAD; m0 += gridDim.x * 128) {
        float acc[2][8][4];
        zero_acc(acc);
        mma_pass_bf(A1, m0, sb, 0, wid, lane, acc);
        mma_pass_f32<false>(A2, m0, sb, TILE_BYTES, wid, lane, acc);

#pragma unroll
        for (int mi = 0; mi < 2; mi++) {
#pragma unroll
            for (int jh = 0; jh < 2; jh++) {
                int row = m0 + wm * 32 + mi * 16 + jh * 8 + r4;
                float2 vals[8];
#pragma unroll
                for (int ni = 0; ni < 8; ni++) {
                    int col = wn * 64 + ni * 8 + c2;
                    float2 b = *(const float2*)(bias + col);
                    vals[ni] = make_float2(acc[mi][ni][jh * 2 + 0] + b.x,
                                           acc[mi][ni][jh * 2 + 1] + b.y);
                }
                store_frag_row(C, row, wn, lane, vals);
            }
        }
    }
}

// ---------------------------------------------------------------------------
// Pool h3 (frag layout) -> Ph; also counts nodes per graph (c==0).
// ---------------------------------------------------------------------------
__global__ __launch_bounds__(128)
void pool_h(const uint4* __restrict__ h, const int* __restrict__ batch,
            float* __restrict__ Ph)
{
    const int n0 = blockIdx.x * 128;
    const int c = threadIdx.x;
    const int cp = c >> 1;
    const int qidx = (cp >> 3) * 4 + (cp & 3);
    const int pos = (cp >> 2) & 1;
    const uint32_t sh = (c & 1) ? 16 : 0;

    int curg = batch[n0];
    float sum = 0.f;
    int cnt = 0;
    for (int i = 0; i < 128; i++) {
        int n = n0 + i;
        if (n >= N_NODES) break;
        int g = batch[n];
        if (g != curg) {
            atomicAdd(&Ph[(size_t)curg * HID + c], sum);
            if (c == 0) atomicAdd(&g_cnt[curg], cnt);
            sum = 0.f; cnt = 0;
            curg = g;
        }
        uint4 v = h[(size_t)n * 32 + qidx];
        uint32_t uh = pos ? v.y : v.x;
        uint32_t ul = pos ? v.w : v.z;
        float hi = __half2float(__ushort_as_half((unsigned short)((uh >> sh) & 0xFFFF)));
        float lo = __half2float(__ushort_as_half((unsigned short)((ul >> sh) & 0xFFFF)));
        sum += hi + lo;
        cnt++;
    }
    atomicAdd(&Ph[(size_t)curg * HID + c], sum);
    if (c == 0) atomicAdd(&g_cnt[curg], cnt);
}

// Pool agg3 (fp32) -> Pa.
__global__ __launch_bounds__(128)
void pool_a(const float* __restrict__ agg, const int* __restrict__ batch,
            float* __restrict__ Pa)
{
    const int n0 = blockIdx.x * 128;
    const int c = threadIdx.x;
    int curg = batch[n0];
    float sum = 0.f;
    for (int i = 0; i < 128; i++) {
        int n = n0 + i;
        if (n >= N_NODES) break;
        int g = batch[n];
        if (g != curg) {
            atomicAdd(&Pa[(size_t)curg * HID + c], sum);
            sum = 0.f;
            curg = g;
        }
        sum += agg[(size_t)n * HID + c];
    }
    atomicAdd(&Pa[(size_t)curg * HID + c], sum);
}

// out[g,:] = Ph[g,:]@Wh_a + Pa[g,:]@Wh_b + cnt[g]*bh   (fp32, layer 3 weights)
__global__ __launch_bounds__(128)
void out_gemm(const float* __restrict__ Ph, const float* __restrict__ Pa,
              const float* __restrict__ Wh3, const float* __restrict__ bh3,
              float* __restrict__ out)
{
    __shared__ float ph[128], pa[128];
    const int g = blockIdx.x;
    const int c = threadIdx.x;
    ph[c] = Ph[(size_t)g * HID + c];
    pa[c] = Pa[(size_t)g * HID + c];
    __syncthreads();
    float acc = (float)g_cnt[g] * bh3[c];
    const float* Wa = Wh3;
    const float* Wb = Wh3 + 128 * HID;
#pragma unroll 8
    for (int k = 0; k < 128; k++) {
        acc += ph[k] * Wa[k * HID + c];
        acc += pa[k] * Wb[k * HID + c];
    }
    out[(size_t)g * HID + c] = acc;
}

// ---------------------------------------------------------------------------
// Launch
// ---------------------------------------------------------------------------
extern "C" void kernel_launch(void* const* d_in, const int* in_sizes, int n_in,
                              void* d_out, int out_size)
{
    const float* h_in     = (const float*)d_in[0];
    const float* e_in     = (const float*)d_in[1];
    const int*   edge_idx = (const int*)d_in[2];
    const int*   batch    = (const int*)d_in[3];
    const float* W_embed  = (const float*)d_in[4];
    const float* b_embed  = (const float*)d_in[5];
    const float* W_eembed = (const float*)d_in[6];
    const float* b_eembed = (const float*)d_in[7];
    const float* Wm       = (const float*)d_in[8];
    const float* bm       = (const float*)d_in[9];
    const float* Wh       = (const float*)d_in[10];
    const float* bh       = (const float*)d_in[11];
    const float* We       = (const float*)d_in[12];
    const float* be       = (const float*)d_in[13];
    float*       out      = (float*)d_out;

    cudaFuncSetAttribute(gh_gemm,    cudaFuncAttributeMaxDynamicSharedMemorySize, SMEM_2);
    cudaFuncSetAttribute(uv_gemm,    cudaFuncAttributeMaxDynamicSharedMemorySize, SMEM_2);
    cudaFuncSetAttribute(hnew_gemm,  cudaFuncAttributeMaxDynamicSharedMemorySize, SMEM_2);
    cudaFuncSetAttribute(embed_gemm, cudaFuncAttributeMaxDynamicSharedMemorySize, SMEM_1);
    cudaFuncSetAttribute(smfour,     cudaFuncAttributeMaxDynamicSharedMemorySize, SMEM_1);

    uint4 *hbuf, *uvbuf, *bw;
    float *Tp, *Sp, *Gp, *aggp, *Ew, *dvecp, *Php, *Pap, *basep;
    int *degp, *cntp;
    cudaGetSymbolAddress((void**)&hbuf, g_hbf);
    cudaGetSymbolAddress((void**)&uvbuf, g_uv);
    cudaGetSymbolAddress((void**)&Tp,   g_T);
    cudaGetSymbolAddress((void**)&Sp,   g_S);
    cudaGetSymbolAddress((void**)&Gp,   g_G);
    cudaGetSymbolAddress((void**)&aggp, g_agg);
    cudaGetSymbolAddress((void**)&degp, g_deg);
    cudaGetSymbolAddress((void**)&Ew,   g_Ew);
    cudaGetSymbolAddress((void**)&bw,   g_Bw);
    cudaGetSymbolAddress((void**)&dvecp, g_dvec);
    cudaGetSymbolAddress((void**)&Php,  g_Ph);
    cudaGetSymbolAddress((void**)&Pap,  g_Pa);
    cudaGetSymbolAddress((void**)&cntp, g_cnt);
    cudaGetSymbolAddress((void**)&basep, g_aggbase);

    uint4* hb[2] = { hbuf, hbuf + (size_t)N_PAD * 32 };
    uint4* ub[2] = { uvbuf, uvbuf + (size_t)N_PAD * 32 };
    uint4* vb[2] = { uvbuf + 2 * (size_t)N_PAD * 32, uvbuf + 3 * (size_t)N_PAD * 32 };
    float* Eb[2] = { Ew, Ew + 16384 };
    const int* send = edge_idx;
    const int* rec  = edge_idx + N_EDGES;

    // Prep
    cudaMemsetAsync(degp, 0, N_PAD * sizeof(int));
    cudaMemsetAsync(Tp, 0, (size_t)N_PAD * 16 * sizeof(float));
    count_deg<<<(N_EDGES + 255) / 256, 256>>>(rec);
    scatter_T<<<4096, 256>>>(e_in, rec, Tp);
    prep_weights<<<34, 256>>>(W_embed, Wm, Wh, We);
    // E-chain: first compose reads We_e_0 directly (no init_E)
    for (int l = 1; l < N_LAYERS; l++) {
        const float* Eold = (l == 1) ? (We + 256 * HID) : Eb[l & 1];   // l=2->Eb[0], l=3->Eb[1]
        compose_kernel<<<dim3(2, 8), 256>>>(
            Eold,
            Wm + (size_t)l * 49152 + 32768,
            We + (size_t)l * 49152 + 32768,
            bw + (size_t)(1 + l * 9 + 8) * 2176,
            Eb[(l - 1) & 1]);                                          // l=1->Eb[0], l=2->Eb[1], l=3->Eb[0]
    }
    dc_kernel<<<1, 128>>>(bm, Wm, be, We);
    s_gemm<<<2048, 128>>>(Tp, W_eembed, b_eembed, Sp);
    embed_gemm<<<296, GT, SMEM_1>>>(h_in, 0, b_embed, hb[0]);
    smfour<<<dim3(4, 148), GT, SMEM_1>>>(Sp);

    int cur = 0, uvcur = 0;
    for (int l = 0; l < N_LAYERS; l++) {
        int sbase = 1 + l * 9;
        int hasUV = (l > 0) ? 1 : 0;
        uint4* hcur = hb[cur];
        uint4* hnxt = hb[1 - cur];

        // G = h@Wm_s (+u@Wm_e); agg = aggbase_l + deg*(h@Wm_r (+v@Wm_e) + d_l)
        gh_gemm<<<dim3(2, 148), GT, SMEM_2>>>(
            hcur, ub[uvcur], vb[uvcur], sbase, hasUV, dvecp + l * HID,
            basep + (size_t)l * N_PAD * HID, Gp, aggp);

        // agg[r] += G[s] over edges
        scatter_G<<<2048, 256>>>(Gp, send, rec, aggp);

        if (l < N_LAYERS - 1) {
            // u' = h@We_s (+u@We_e); v' = h@We_r (+v@We_e)
            uv_gemm<<<dim3(2, 148), GT, SMEM_2>>>(
                hcur, ub[uvcur], vb[uvcur], sbase, hasUV,
                ub[1 - uvcur], vb[1 - uvcur]);
            uvcur = 1 - uvcur;

            // h' = h@Wh_a + agg@Wh_b + bh
            hnew_gemm<<<296, GT, SMEM_2>>>(hcur, sbase + 6, aggp, sbase + 7,
                                           bh + (size_t)l * HID, hnxt);
            cur = 1 - cur;
        }
    }

    // Final: out = pool(h3)@Wh_a3 + pool(agg3)@Wh_b3 + cnt*bh3
    cudaMemsetAsync(Php, 0, NUM_GRAPHS * HID * sizeof(float));
    cudaMemsetAsync(Pap, 0, NUM_GRAPHS * HID * sizeof(float));
    cudaMemsetAsync(cntp, 0, NUM_GRAPHS * sizeof(int));
    pool_h<<<313, 128>>>(hb[cur], batch, Php);
    pool_a<<<313, 128>>>(aggp, batch, Pap);
    out_gemm<<<NUM_GRAPHS, 128>>>(Php, Pap,
                                  Wh + (size_t)3 * 256 * HID, bh + (size_t)3 * HID, out);
}

// round 17
// speedup vs baseline: 1.4796x; 1.0491x over previous
#include <cuda_runtime.h>
#include <cuda_fp16.h>
#include <cstdint>

#define N_NODES 40000
#define N_PAD   40064   // 313 * 128
#define N_EDGES 640000
#define HID 128
#define N_LAYERS 4
#define NUM_GRAPHS 256

#define GT 256          // 8 warps per GEMM CTA

#define LDB 272
#define TILE_BYTES 34816
#define SMEM_1 34816
#define SMEM_2 69632

// ---------------------------------------------------------------------------
// Scratch
// ---------------------------------------------------------------------------
__device__ uint4 g_hbf[2][(size_t)N_PAD * 32];
__device__ uint4 g_uv[4][(size_t)N_PAD * 32];      // u0,u1,v0,v1 ping-pong
__device__ float g_T[(size_t)N_PAD * 16];          // scattered raw edge feats
__device__ float g_S[(size_t)N_PAD * HID];         // S = T@W_eembed + deg*b
__device__ float g_G[(size_t)N_PAD * HID];         // send-side gather array (fp32)
__device__ float g_agg[(size_t)N_PAD * HID];
__device__ float g_aggbase[N_LAYERS][(size_t)N_PAD * HID];  // S@M_l
__device__ int   g_deg[N_PAD];
__device__ float g_Ew[2][16384];                   // E_l chain (fp32, ping-pong)
__device__ float g_dvec[N_LAYERS * HID];           // d_l vectors
__device__ float g_Ph[NUM_GRAPHS * HID];           // pooled h3
__device__ float g_Pa[NUM_GRAPHS * HID];           // pooled agg3
__device__ int   g_cnt[NUM_GRAPHS];                // nodes per graph
// 37 weight slots (fp16 padded [n][k] images): 0=W_embed; layer base=1+9l:
// +0 Wm_s +1 Wm_r +2 Wm_e +3 We_s +4 We_r +5 We_e +6 Wh_a +7 Wh_b +8 M_l
__device__ uint4 g_Bw[(size_t)37 * 2176];

// ---------------------------------------------------------------------------
// PTX helpers
// ---------------------------------------------------------------------------
__device__ __forceinline__ uint32_t smem_u32(const void* p) {
    uint32_t a;
    asm("{ .reg .u64 t; cvta.to.shared.u64 t, %1; cvt.u32.u64 %0, t; }" : "=r"(a) : "l"(p));
    return a;
}
__device__ __forceinline__ void red_add_v4(float* addr, float a, float b, float c, float d) {
    asm volatile("red.global.add.v4.f32 [%0], {%1, %2, %3, %4};"
                 :: "l"(addr), "f"(a), "f"(b), "f"(c), "f"(d) : "memory");
}
__device__ __forceinline__ void ldsm_x4(uint32_t addr, uint32_t r[4]) {
    asm volatile("ldmatrix.sync.aligned.m8n8.x4.shared.b16 {%0,%1,%2,%3}, [%4];"
                 : "=r"(r[0]), "=r"(r[1]), "=r"(r[2]), "=r"(r[3]) : "r"(addr));
}
__device__ __forceinline__ void mma_f16(float c[4], const uint32_t a[4], uint32_t b0, uint32_t b1) {
    asm volatile("mma.sync.aligned.m16n8k16.row.col.f32.f16.f16.f32 "
                 "{%0,%1,%2,%3}, {%4,%5,%6,%7}, {%8,%9}, {%0,%1,%2,%3};"
                 : "+f"(c[0]), "+f"(c[1]), "+f"(c[2]), "+f"(c[3])
                 : "r"(a[0]), "r"(a[1]), "r"(a[2]), "r"(a[3]), "r"(b0), "r"(b1));
}
__device__ __forceinline__ uint32_t pack_hi_lo(float a, float b, uint32_t& lo_out) {
    __half ha = __float2half_rn(a), hb = __float2half_rn(b);
    float ra = a - __half2float(ha), rb = b - __half2float(hb);
    __half la = __float2half_rn(ra), lb = __float2half_rn(rb);
    lo_out = (uint32_t)__half_as_ushort(la) | ((uint32_t)__half_as_ushort(lb) << 16);
    return (uint32_t)__half_as_ushort(ha) | ((uint32_t)__half_as_ushort(hb) << 16);
}

__device__ __forceinline__ void stage_B(int slot, int tid, char* smem, int off)
{
    const uint4* src = g_Bw + (size_t)slot * 2176;
    uint4* dst = (uint4*)(smem + off);
#pragma unroll
    for (int i = 0; i < 9; i++) {
        int idx = tid + i * 256;
        if (idx < 2176) dst[idx] = src[idx];
    }
}

// ---------------------------------------------------------------------------
// A loaders
// ---------------------------------------------------------------------------
__device__ __forceinline__ void load_A4(const uint4* __restrict__ A, int row0, int ks,
                                        int lane, uint4 av[4])
{
    const uint4* base = A + (size_t)(row0 + (lane >> 2)) * 32 + ks * 4 + (lane & 3);
#pragma unroll
    for (int mi = 0; mi < 2; mi++)
#pragma unroll
        for (int jh = 0; jh < 2; jh++)
            av[mi * 2 + jh] = base[(size_t)(mi * 16 + jh * 8) * 32];
}
template<bool GUARD>
__device__ __forceinline__ void load_A_raw(const float* __restrict__ A, int row0, int k0,
                                           int lane, float2 av[8])
{
    const int r = row0 + (lane >> 2);
    const int c = k0 + (lane & 3) * 2;
#pragma unroll
    for (int mi = 0; mi < 2; mi++)
#pragma unroll
        for (int jh = 0; jh < 2; jh++) {
            int row = r + mi * 16 + jh * 8;
            const float* rp = A + (size_t)row * HID + c;
#pragma unroll
            for (int jc = 0; jc < 2; jc++) {
                float2 v = make_float2(0.f, 0.f);
                if (!GUARD || row < N_NODES) v = *(const float2*)(rp + jc * 8);
                av[mi * 4 + jh + 2 * jc] = v;
            }
        }
}

// ---------------------------------------------------------------------------
// 32-MMA inner block (2-product fp16 emulation)
// ---------------------------------------------------------------------------
__device__ __forceinline__ void mma_block(const uint32_t ah[8], const uint32_t al[8],
                                          uint32_t bBase, uint32_t ko, float acc[2][8][4])
{
#pragma unroll
    for (int nb = 0; nb < 4; nb++) {
        uint32_t bh[4];
        ldsm_x4(bBase + nb * 16 * LDB + ko, bh);
#pragma unroll
        for (int half = 0; half < 2; half++) {
            const int ni = nb * 2 + half;
#pragma unroll
            for (int mi = 0; mi < 2; mi++) {
                mma_f16(acc[mi][ni], &ah[mi * 4], bh[half], bh[half + 2]);
                mma_f16(acc[mi][ni], &al[mi * 4], bh[half], bh[half + 2]);
            }
        }
    }
}

__device__ __forceinline__ void mma_pass_bf(const uint4* __restrict__ A, int m0,
                                            uint32_t sb, int bOff, int wid, int lane,
                                            float acc[2][8][4])
{
    const int wm = wid & 3, wn = wid >> 2;
    const uint32_t lrow = (uint32_t)((lane & 15) * LDB + (lane >> 4) * 16);
    const uint32_t bBase = sb + bOff + wn * 64 * LDB + lrow;
    const int row0 = m0 + wm * 32;

    uint4 av[4];
    load_A4(A, row0, 0, lane, av);
#pragma unroll
    for (int ks = 0; ks < 8; ks++) {
        uint32_t ah[8], al[8];
#pragma unroll
        for (int s = 0; s < 4; s++) {
            const int mi = s >> 1, jh = s & 1;
            ah[mi * 4 + jh]     = av[s].x;
            ah[mi * 4 + jh + 2] = av[s].y;
            al[mi * 4 + jh]     = av[s].z;
            al[mi * 4 + jh + 2] = av[s].w;
        }
        if (ks < 7) load_A4(A, row0, ks + 1, lane, av);
        mma_block(ah, al, bBase, (uint32_t)(ks * 32), acc);
    }
}

template<bool GUARD>
__device__ __forceinline__ void mma_pass_f32(const float* __restrict__ A, int m0,
                                             uint32_t sb, int bOff, int wid, int lane,
                                             float acc[2][8][4])
{
    const int wm = wid & 3, wn = wid >> 2;
    const uint32_t lrow = (uint32_t)((lane & 15) * LDB + (lane >> 4) * 16);
    const uint32_t bBase = sb + bOff + wn * 64 * LDB + lrow;
    const int row0 = m0 + wm * 32;

    float2 av[8];
    load_A_raw<GUARD>(A, row0, 0, lane, av);
#pragma unroll
    for (int ks = 0; ks < 8; ks++) {
        uint32_t ah[8], al[8];
#pragma unroll
        for (int i = 0; i < 8; i++) ah[i] = pack_hi_lo(av[i].x, av[i].y, al[i]);
        if (ks < 7) load_A_raw<GUARD>(A, row0, (ks + 1) * 16, lane, av);
        mma_block(ah, al, bBase, (uint32_t)(ks * 32), acc);
    }
}

__device__ __forceinline__ void zero_acc(float acc[2][8][4]) {
#pragma unroll
    for (int mi = 0; mi < 2; mi++)
#pragma unroll
        for (int ni = 0; ni < 8; ni++)
#pragma unroll
            for (int j = 0; j < 4; j++) acc[mi][ni][j] = 0.f;
}

__device__ __forceinline__ void store_frag_row(uint4* __restrict__ C, int row, int wn, int lane,
                                               const float2 vals[8])
{
    uint4* Cp = C + (size_t)row * 32 + (lane & 3);
#pragma unroll
    for (int ni2 = 0; ni2 < 8; ni2 += 2) {
        uint4 v;
        v.x = pack_hi_lo(vals[ni2].x,     vals[ni2].y,     v.z);
        v.y = pack_hi_lo(vals[ni2 + 1].x, vals[ni2 + 1].y, v.w);
        Cp[(size_t)(wn * 4 + (ni2 >> 1)) * 4] = v;
    }
}

// ---------------------------------------------------------------------------
// Weight prep
// ---------------------------------------------------------------------------
__global__ __launch_bounds__(256)
void prep_weights(const float* __restrict__ W_embed, const float* __restrict__ Wm,
                  const float* __restrict__ Wh, const float* __restrict__ We)
{
    int t = blockIdx.x;
    const float* src;
    int slot;
    if (t == 0) { src = W_embed; slot = 0; }
    else if (t == 33) { src = Wm + 256 * HID; slot = 9; }   // M_0 = Wm_e_0
    else {
        int tt = t - 1, l = tt >> 3, j = tt & 7;
        slot = 1 + l * 9 + j;
        if (j < 3)      src = Wm + (size_t)l * 384 * HID + j * 16384;
        else if (j < 6) src = We + (size_t)l * 384 * HID + (j - 3) * 16384;
        else            src = Wh + (size_t)l * 256 * HID + (j - 6) * 16384;
    }
    char* dst = (char*)(g_Bw + (size_t)slot * 2176);
    for (int i = threadIdx.x; i < 16384; i += 256) {
        int k = i >> 7, n = i & 127;
        *(__half*)(dst + (uint32_t)(n * LDB + k * 2)) = __float2half_rn(src[i]);
    }
}

// Compose: grid (2, 8), B staged in SMEM (64KB).
// x=0: M_l image = fp16(Eold @ Wm_e); x=1: Enew = Eold @ We_e
__global__ __launch_bounds__(256)
void compose_kernel(const float* __restrict__ Eold, const float* __restrict__ Wm_e,
                    const float* __restrict__ We_e, uint4* __restrict__ slotimg,
                    float* __restrict__ Enew)
{
    extern __shared__ float Bs[];   // 16384 floats = 64KB
    const float* B = blockIdx.x ? We_e : Wm_e;
    for (int i = threadIdx.x; i < 4096; i += 256)
        *(float4*)(Bs + i * 4) = *(const float4*)(B + i * 4);
    __syncthreads();

    const int i = blockIdx.y * 16 + (threadIdx.x >> 4);
    const int j0 = (threadIdx.x & 15) * 8;
    float acc[8];
#pragma unroll
    for (int j = 0; j < 8; j++) acc[j] = 0.f;
#pragma unroll 16
    for (int k = 0; k < 128; k++) {
        float a = Eold[i * 128 + k];
        const float* br = Bs + k * 128 + j0;
#pragma unroll
        for (int j = 0; j < 8; j++) acc[j] += a * br[j];
    }
    if (blockIdx.x == 0) {
        char* dst = (char*)slotimg;
#pragma unroll
        for (int j = 0; j < 8; j++)
            *(__half*)(dst + (uint32_t)((j0 + j) * LDB + i * 2)) = __float2half_rn(acc[j]);
    } else {
#pragma unroll
        for (int j = 0; j < 8; j++) Enew[i * 128 + j0 + j] = acc[j];
    }
}

// c/d chain: d_l = bm_l + c_l@Wm_e_l ; c_{l+1} = c_l@We_e_l + be_l
__global__ __launch_bounds__(128)
void dc_kernel(const float* __restrict__ bm, const float* __restrict__ Wm,
               const float* __restrict__ be, const float* __restrict__ We)
{
    __shared__ float c[128], cn[128];
    const int j = threadIdx.x;
    c[j] = 0.f;
    __syncthreads();
    for (int l = 0; l < N_LAYERS; l++) {
        const float* Wme = Wm + (size_t)l * 49152 + 32768;
        const float* Wee = We + (size_t)l * 49152 + 32768;
        float dj = bm[l * 128 + j], cj = be[l * 128 + j];
#pragma unroll 8
        for (int k = 0; k < 128; k++) {
            dj += c[k] * Wme[k * 128 + j];
            cj += c[k] * Wee[k * 128 + j];
        }
        g_dvec[l * 128 + j] = dj;
        cn[j] = cj;
        __syncthreads();
        c[j] = cn[j];
        __syncthreads();
    }
}

// Scatter raw edge features + degree: T[rec,:] += e_in[e,:]; deg[rec]++
__global__ __launch_bounds__(256)
void scatter_T(const float* __restrict__ e_in, const int* __restrict__ rec,
               float* __restrict__ T)
{
    int gid = blockIdx.x * 256 + threadIdx.x;
    const int total = N_EDGES * 4;
    for (int i = gid; i < total; i += gridDim.x * 256) {
        int e = i >> 2, p = (i & 3) * 4;
        int r = rec[e];
        float4 v = *(const float4*)(e_in + (size_t)e * 16 + p);
        red_add_v4(T + (size_t)r * 16 + p, v.x, v.y, v.z, v.w);
        if ((i & 3) == 0) atomicAdd(&g_deg[r], 1);
    }
}

// S = T @ W_eembed + deg * b_eembed
__global__ __launch_bounds__(128)
void s_gemm(const float* __restrict__ T, const float* __restrict__ W,
            const float* __restrict__ b, float* __restrict__ S)
{
    __shared__ float Ws[16 * 128];
    __shared__ float bs[128];
    for (int i = threadIdx.x; i < 16 * 128; i += blockDim.x) Ws[i] = W[i];
    if (threadIdx.x < 128) bs[threadIdx.x] = b[threadIdx.x];
    __syncthreads();
    const int c = threadIdx.x;
    for (int n = blockIdx.x; n < N_PAD; n += gridDim.x) {
        const float* tr = T + (size_t)n * 16;
        float acc = (float)g_deg[n] * bs[c];
#pragma unroll
        for (int j = 0; j < 16; j++) acc += tr[j] * Ws[j * 128 + c];
        S[(size_t)n * HID + c] = acc;
    }
}

// ---------------------------------------------------------------------------
// smfour: grid (4, GY). aggbase[y] = S @ M_y for all layers in one launch.
// ---------------------------------------------------------------------------
__global__ __launch_bounds__(GT, 2)
void smfour(const float* __restrict__ S)
{
    extern __shared__ char smem[];
    uint32_t sb = smem_u32(smem);
    const int tid = threadIdx.x, wid = tid >> 5, lane = tid & 31;
    const int y = blockIdx.x;
    const int wm = wid & 3, wn = wid >> 2;
    const int r4 = lane >> 2, c2 = (lane & 3) * 2;
    float* outp = g_aggbase[y];

    stage_B(1 + y * 9 + 8, tid, smem, 0);
    __syncthreads();

    for (int m0 = blockIdx.y * 128; m0 < N_PAD; m0 += gridDim.y * 128) {
        float acc[2][8][4];
        zero_acc(acc);
        mma_pass_f32<false>(S, m0, sb, 0, wid, lane, acc);

#pragma unroll
        for (int mi = 0; mi < 2; mi++) {
#pragma unroll
            for (int jh = 0; jh < 2; jh++) {
                int row = m0 + wm * 32 + mi * 16 + jh * 8 + r4;
                float* Cp = outp + (size_t)row * HID;
#pragma unroll
                for (int ni = 0; ni < 8; ni++) {
                    int col = wn * 64 + ni * 8 + c2;
                    *(float2*)(Cp + col) = make_float2(acc[mi][ni][jh * 2 + 0],
                                                       acc[mi][ni][jh * 2 + 1]);
                }
            }
        }
    }
}

// ---------------------------------------------------------------------------
// gh_gemm: grid (2, GY).
//  y=0: G   = h@Wm_s (+ u@Wm_e)
//  y=1: agg = aggbase_l + deg*(h@Wm_r (+ v@Wm_e) + d_l)
// ---------------------------------------------------------------------------
__global__ __launch_bounds__(GT, 2)
void gh_gemm(const uint4* __restrict__ h, const uint4* __restrict__ u,
             const uint4* __restrict__ v, int sbase, int hasUV,
             const float* __restrict__ dvec, const float* __restrict__ base,
             float* __restrict__ G, float* __restrict__ agg)
{
    extern __shared__ char smem[];
    uint32_t sb = smem_u32(smem);
    const int tid = threadIdx.x, wid = tid >> 5, lane = tid & 31;
    const int y = blockIdx.x;
    const int wm = wid & 3, wn = wid >> 2;
    const int r4 = lane >> 2, c2 = (lane & 3) * 2;
    const uint4* A2 = y ? v : u;

    stage_B(sbase + (y ? 1 : 0), tid, smem, 0);
    if (hasUV) stage_B(sbase + 2, tid, smem, TILE_BYTES);
    __syncthreads();

    for (int m0 = blockIdx.y * 128; m0 < N_PAD; m0 += gridDim.y * 128) {
        float acc[2][8][4];
        zero_acc(acc);
        mma_pass_bf(h, m0, sb, 0, wid, lane, acc);
        if (hasUV) mma_pass_bf(A2, m0, sb, TILE_BYTES, wid, lane, acc);

        if (y == 1) {
#pragma unroll
            for (int mi = 0; mi < 2; mi++) {
#pragma unroll
                for (int jh = 0; jh < 2; jh++) {
                    int row = m0 + wm * 32 + mi * 16 + jh * 8 + r4;
                    float d = (float)g_deg[row];
                    const float* Bp = base + (size_t)row * HID;
                    float* Cp = agg + (size_t)row * HID;
#pragma unroll
                    for (int ni = 0; ni < 8; ni++) {
                        int col = wn * 64 + ni * 8 + c2;
                        float2 b = *(const float2*)(dvec + col);
                        float2 o = *(const float2*)(Bp + col);
                        *(float2*)(Cp + col) = make_float2(
                            o.x + d * (acc[mi][ni][jh * 2 + 0] + b.x),
                            o.y + d * (acc[mi][ni][jh * 2 + 1] + b.y));
                    }
                }
            }
        } else {
#pragma unroll
            for (int mi = 0; mi < 2; mi++) {
#pragma unroll
                for (int jh = 0; jh < 2; jh++) {
                    int row = m0 + wm * 32 + mi * 16 + jh * 8 + r4;
                    float* Cp = G + (size_t)row * HID;
#pragma unroll
                    for (int ni = 0; ni < 8; ni++) {
                        int col = wn * 64 + ni * 8 + c2;
                        *(float2*)(Cp + col) = make_float2(acc[mi][ni][jh * 2 + 0],
                                                           acc[mi][ni][jh * 2 + 1]);
                    }
                }
            }
        }
    }
}

// ---------------------------------------------------------------------------
// uv_gemm: grid (2, GY). y=0: u' = h@We_s (+ u@We_e); y=1: v' = h@We_r (+ v@We_e)
// ---------------------------------------------------------------------------
__global__ __launch_bounds__(GT, 2)
void uv_gemm(const uint4* __restrict__ h, const uint4* __restrict__ u,
             const uint4* __restrict__ v, int sbase, int hasUV,
             uint4* __restrict__ uout, uint4* __restrict__ vout)
{
    extern __shared__ char smem[];
    uint32_t sb = smem_u32(smem);
    const int tid = threadIdx.x, wid = tid >> 5, lane = tid & 31;
    const int y = blockIdx.x;
    const int wm = wid & 3, wn = wid >> 2;
    const int r4 = lane >> 2, c2 = (lane & 3) * 2;
    const uint4* A2 = y ? v : u;
    uint4* C = y ? vout : uout;

    stage_B(sbase + (y ? 4 : 3), tid, smem, 0);
    if (hasUV) stage_B(sbase + 5, tid, smem, TILE_BYTES);
    __syncthreads();

    for (int m0 = blockIdx.y * 128; m0 < N_PAD; m0 += gridDim.y * 128) {
        float acc[2][8][4];
        zero_acc(acc);
        mma_pass_bf(h, m0, sb, 0, wid, lane, acc);
        if (hasUV) mma_pass_bf(A2, m0, sb, TILE_BYTES, wid, lane, acc);

#pragma unroll
        for (int mi = 0; mi < 2; mi++) {
#pragma unroll
            for (int jh = 0; jh < 2; jh++) {
                int row = m0 + wm * 32 + mi * 16 + jh * 8 + r4;
                float2 vals[8];
#pragma unroll
                for (int ni = 0; ni < 8; ni++) {
                    vals[ni] = make_float2(acc[mi][ni][jh * 2 + 0],
                                           acc[mi][ni][jh * 2 + 1]);
                }
                store_frag_row(C, row, wn, lane, vals);
            }
        }
    }
}

// ---------------------------------------------------------------------------
// scatter_G: agg[rec[e], :] += G[send[e], :]
// ---------------------------------------------------------------------------
__global__ __launch_bounds__(256)
void scatter_G(const float* __restrict__ G, const int* __restrict__ send,
               const int* __restrict__ rec, float* __restrict__ agg)
{
    const int w = (blockIdx.x * 256 + threadIdx.x) >> 5;
    const int lane = threadIdx.x & 31;
    const int nwarp = gridDim.x * 8;
    for (int e = w; e < N_EDGES; e += nwarp) {
        int s = send[e], r = rec[e];
        float4 v = *(const float4*)(G + (size_t)s * HID + lane * 4);
        red_add_v4(agg + (size_t)r * HID + lane * 4, v.x, v.y, v.z, v.w);
    }
}

// ---------------------------------------------------------------------------
// embed_gemm: C_frag = h_in(fp32, guarded) @ B0 + bias
// ---------------------------------------------------------------------------
__global__ __launch_bounds__(GT, 2)
void embed_gemm(const float* __restrict__ A, int slot,
                const float* __restrict__ bias, uint4* __restrict__ C)
{
    extern __shared__ char smem[];
    uint32_t sb = smem_u32(smem);
    const int tid = threadIdx.x, wid = tid >> 5, lane = tid & 31;
    const int wm = wid & 3, wn = wid >> 2;
    const int r4 = lane >> 2, c2 = (lane & 3) * 2;

    stage_B(slot, tid, smem, 0);
    __syncthreads();

    for (int m0 = blockIdx.x * 128; m0 < N_PAD; m0 += gridDim.x * 128) {
        float acc[2][8][4];
        zero_acc(acc);
        mma_pass_f32<true>(A, m0, sb, 0, wid, lane, acc);

#pragma unroll
        for (int mi = 0; mi < 2; mi++) {
#pragma unroll
            for (int jh = 0; jh < 2; jh++) {
                int row = m0 + wm * 32 + mi * 16 + jh * 8 + r4;
                float2 vals[8];
#pragma unroll
                for (int ni = 0; ni < 8; ni++) {
                    int col = wn * 64 + ni * 8 + c2;
                    float2 b = *(const float2*)(bias + col);
                    vals[ni] = make_float2(acc[mi][ni][jh * 2 + 0] + b.x,
                                           acc[mi][ni][jh * 2 + 1] + b.y);
                }
                store_frag_row(C, row, wn, lane, vals);
            }
        }
    }
}

// ---------------------------------------------------------------------------
// hnew_gemm: C_frag = h@Wh_a + agg(fp32)@Wh_b + bias
// ---------------------------------------------------------------------------
__global__ __launch_bounds__(GT, 2)
void hnew_gemm(const uint4* __restrict__ A1, int slot1,
               const float* __restrict__ A2, int slot2,
               const float* __restrict__ bias, uint4* __restrict__ C)
{
    extern __shared__ char smem[];
    uint32_t sb = smem_u32(smem);
    const int tid = threadIdx.x, wid = tid >> 5, lane = tid & 31;
    const int wm = wid & 3, wn = wid >> 2;
    const int r4 = lane >> 2, c2 = (lane & 3) * 2;

    stage_B(slot1, tid, smem, 0);
    stage_B(slot2, tid, smem, TILE_BYTES);
    __syncthreads();

    for (int m0 = blockIdx.x * 128; m0 < N_PAD; m0 += gridDim.x * 128) {
        float acc[2][8][4];
        zero_acc(acc);
        mma_pass_bf(A1, m0, sb, 0, wid, lane, acc);
        mma_pass_f32<false>(A2, m0, sb, TILE_BYTES, wid, lane, acc);

#pragma unroll
        for (int mi = 0; mi < 2; mi++) {
#pragma unroll
            for (int jh = 0; jh < 2; jh++) {
                int row = m0 + wm * 32 + mi * 16 + jh * 8 + r4;
                float2 vals[8];
#pragma unroll
                for (int ni = 0; ni < 8; ni++) {
                    int col = wn * 64 + ni * 8 + c2;
                    float2 b = *(const float2*)(bias + col);
                    vals[ni] = make_float2(acc[mi][ni][jh * 2 + 0] + b.x,
                                           acc[mi][ni][jh * 2 + 1] + b.y);
                }
                store_frag_row(C, row, wn, lane, vals);
            }
        }
    }
}

// ---------------------------------------------------------------------------
// Pool h3 (frag layout) -> Ph; also counts nodes per graph (c==0).
// ---------------------------------------------------------------------------
__global__ __launch_bounds__(128)
void pool_h(const uint4* __restrict__ h, const int* __restrict__ batch,
            float* __restrict__ Ph)
{
    const int n0 = blockIdx.x * 128;
    const int c = threadIdx.x;
    const int cp = c >> 1;
    const int qidx = (cp >> 3) * 4 + (cp & 3);
    const int pos = (cp >> 2) & 1;
    const uint32_t sh = (c & 1) ? 16 : 0;

    int curg = batch[n0];
    float sum = 0.f;
    int cnt = 0;
    for (int i = 0; i < 128; i++) {
        int n = n0 + i;
        if (n >= N_NODES) break;
        int g = batch[n];
        if (g != curg) {
            atomicAdd(&Ph[(size_t)curg * HID + c], sum);
            if (c == 0) atomicAdd(&g_cnt[curg], cnt);
            sum = 0.f; cnt = 0;
            curg = g;
        }
        uint4 v = h[(size_t)n * 32 + qidx];
        uint32_t uh = pos ? v.y : v.x;
        uint32_t ul = pos ? v.w : v.z;
        float hi = __half2float(__ushort_as_half((unsigned short)((uh >> sh) & 0xFFFF)));
        float lo = __half2float(__ushort_as_half((unsigned short)((ul >> sh) & 0xFFFF)));
        sum += hi + lo;
        cnt++;
    }
    atomicAdd(&Ph[(size_t)curg * HID + c], sum);
    if (c == 0) atomicAdd(&g_cnt[curg], cnt);
}

// Pool agg3 (fp32) -> Pa.
__global__ __launch_bounds__(128)
void pool_a(const float* __restrict__ agg, const int* __restrict__ batch,
            float* __restrict__ Pa)
{
    const int n0 = blockIdx.x * 128;
    const int c = threadIdx.x;
    int curg = batch[n0];
    float sum = 0.f;
    for (int i = 0; i < 128; i++) {
        int n = n0 + i;
        if (n >= N_NODES) break;
        int g = batch[n];
        if (g != curg) {
            atomicAdd(&Pa[(size_t)curg * HID + c], sum);
            sum = 0.f;
            curg = g;
        }
        sum += agg[(size_t)n * HID + c];
    }
    atomicAdd(&Pa[(size_t)curg * HID + c], sum);
}

// out[g,:] = Ph[g,:]@Wh_a + Pa[g,:]@Wh_b + cnt[g]*bh   (fp32, layer 3 weights)
__global__ __launch_bounds__(128)
void out_gemm(const float* __restrict__ Ph, const float* __restrict__ Pa,
              const float* __restrict__ Wh3, const float* __restrict__ bh3,
              float* __restrict__ out)
{
    __shared__ float ph[128], pa[128];
    const int g = blockIdx.x;
    const int c = threadIdx.x;
    ph[c] = Ph[(size_t)g * HID + c];
    pa[c] = Pa[(size_t)g * HID + c];
    __syncthreads();
    float acc = (float)g_cnt[g] * bh3[c];
    const float* Wa = Wh3;
    const float* Wb = Wh3 + 128 * HID;
#pragma unroll 8
    for (int k = 0; k < 128; k++) {
        acc += ph[k] * Wa[k * HID + c];
        acc += pa[k] * Wb[k * HID + c];
    }
    out[(size_t)g * HID + c] = acc;
}

// ---------------------------------------------------------------------------
// Launch
// ---------------------------------------------------------------------------
extern "C" void kernel_launch(void* const* d_in, const int* in_sizes, int n_in,
                              void* d_out, int out_size)
{
    const float* h_in     = (const float*)d_in[0];
    const float* e_in     = (const float*)d_in[1];
    const int*   edge_idx = (const int*)d_in[2];
    const int*   batch    = (const int*)d_in[3];
    const float* W_embed  = (const float*)d_in[4];
    const float* b_embed  = (const float*)d_in[5];
    const float* W_eembed = (const float*)d_in[6];
    const float* b_eembed = (const float*)d_in[7];
    const float* Wm       = (const float*)d_in[8];
    const float* bm       = (const float*)d_in[9];
    const float* Wh       = (const float*)d_in[10];
    const float* bh       = (const float*)d_in[11];
    const float* We       = (const float*)d_in[12];
    const float* be       = (const float*)d_in[13];
    float*       out      = (float*)d_out;

    cudaFuncSetAttribute(gh_gemm,    cudaFuncAttributeMaxDynamicSharedMemorySize, SMEM_2);
    cudaFuncSetAttribute(uv_gemm,    cudaFuncAttributeMaxDynamicSharedMemorySize, SMEM_2);
    cudaFuncSetAttribute(hnew_gemm,  cudaFuncAttributeMaxDynamicSharedMemorySize, SMEM_2);
    cudaFuncSetAttribute(embed_gemm, cudaFuncAttributeMaxDynamicSharedMemorySize, SMEM_1);
    cudaFuncSetAttribute(smfour,     cudaFuncAttributeMaxDynamicSharedMemorySize, SMEM_1);
    cudaFuncSetAttribute(compose_kernel, cudaFuncAttributeMaxDynamicSharedMemorySize, 65536);

    uint4 *hbuf, *uvbuf, *bw;
    float *Tp, *Sp, *Gp, *aggp, *Ew, *dvecp, *Php, *Pap, *basep;
    int *degp, *cntp;
    cudaGetSymbolAddress((void**)&hbuf, g_hbf);
    cudaGetSymbolAddress((void**)&uvbuf, g_uv);
    cudaGetSymbolAddress((void**)&Tp,   g_T);
    cudaGetSymbolAddress((void**)&Sp,   g_S);
    cudaGetSymbolAddress((void**)&Gp,   g_G);
    cudaGetSymbolAddress((void**)&aggp, g_agg);
    cudaGetSymbolAddress((void**)&degp, g_deg);
    cudaGetSymbolAddress((void**)&Ew,   g_Ew);
    cudaGetSymbolAddress((void**)&bw,   g_Bw);
    cudaGetSymbolAddress((void**)&dvecp, g_dvec);
    cudaGetSymbolAddress((void**)&Php,  g_Ph);
    cudaGetSymbolAddress((void**)&Pap,  g_Pa);
    cudaGetSymbolAddress((void**)&cntp, g_cnt);
    cudaGetSymbolAddress((void**)&basep, g_aggbase);

    uint4* hb[2] = { hbuf, hbuf + (size_t)N_PAD * 32 };
    uint4* ub[2] = { uvbuf, uvbuf + (size_t)N_PAD * 32 };
    uint4* vb[2] = { uvbuf + 2 * (size_t)N_PAD * 32, uvbuf + 3 * (size_t)N_PAD * 32 };
    float* Eb[2] = { Ew, Ew + 16384 };
    const int* send = edge_idx;
    const int* rec  = edge_idx + N_EDGES;

    // Prep
    cudaMemsetAsync(degp, 0, N_PAD * sizeof(int));
    cudaMemsetAsync(Tp, 0, (size_t)N_PAD * 16 * sizeof(float));
    scatter_T<<<4096, 256>>>(e_in, rec, Tp);              // also counts deg
    prep_weights<<<34, 256>>>(W_embed, Wm, Wh, We);
    // E-chain: first compose reads We_e_0 directly; B staged in SMEM
    for (int l = 1; l < N_LAYERS; l++) {
        const float* Eold = (l == 1) ? (We + 256 * HID) : Eb[l & 1];   // l=2->Eb[0], l=3->Eb[1]
        compose_kernel<<<dim3(2, 8), 256, 65536>>>(
            Eold,
            Wm + (size_t)l * 49152 + 32768,
            We + (size_t)l * 49152 + 32768,
            bw + (size_t)(1 + l * 9 + 8) * 2176,
            Eb[(l - 1) & 1]);                                          // l=1->Eb[0], l=2->Eb[1], l=3->Eb[0]
    }
    dc_kernel<<<1, 128>>>(bm, Wm, be, We);
    s_gemm<<<2048, 128>>>(Tp, W_eembed, b_eembed, Sp);
    embed_gemm<<<296, GT, SMEM_1>>>(h_in, 0, b_embed, hb[0]);
    smfour<<<dim3(4, 148), GT, SMEM_1>>>(Sp);

    int cur = 0, uvcur = 0;
    for (int l = 0; l < N_LAYERS; l++) {
        int sbase = 1 + l * 9;
        int hasUV = (l > 0) ? 1 : 0;
        uint4* hcur = hb[cur];
        uint4* hnxt = hb[1 - cur];

        // G = h@Wm_s (+u@Wm_e); agg = aggbase_l + deg*(h@Wm_r (+v@Wm_e) + d_l)
        gh_gemm<<<dim3(2, 148), GT, SMEM_2>>>(
            hcur, ub[uvcur], vb[uvcur], sbase, hasUV, dvecp + l * HID,
            basep + (size_t)l * N_PAD * HID, Gp, aggp);

        // agg[r] += G[s] over edges
        scatter_G<<<2048, 256>>>(Gp, send, rec, aggp);

        if (l < N_LAYERS - 1) {
            // u' = h@We_s (+u@We_e); v' = h@We_r (+v@We_e)
            uv_gemm<<<dim3(2, 148), GT, SMEM_2>>>(
                hcur, ub[uvcur], vb[uvcur], sbase, hasUV,
                ub[1 - uvcur], vb[1 - uvcur]);
            uvcur = 1 - uvcur;

            // h' = h@Wh_a + agg@Wh_b + bh
            hnew_gemm<<<296, GT, SMEM_2>>>(hcur, sbase + 6, aggp, sbase + 7,
                                           bh + (size_t)l * HID, hnxt);
            cur = 1 - cur;
        }
    }

    // Final: out = pool(h3)@Wh_a3 + pool(agg3)@Wh_b3 + cnt*bh3
    cudaMemsetAsync(Php, 0, NUM_GRAPHS * HID * sizeof(float));
    cudaMemsetAsync(Pap, 0, NUM_GRAPHS * HID * sizeof(float));
    cudaMemsetAsync(cntp, 0, NUM_GRAPHS * sizeof(int));
    pool_h<<<313, 128>>>(hb[cur], batch, Php);
    pool_a<<<313, 128>>>(aggp, batch, Pap);
    out_gemm<<<NUM_GRAPHS, 128>>>(Php, Pap,
                                  Wh + (size_t)3 * 256 * HID, bh + (size_t)3 * HID, out);
}